// round 12
// baseline (speedup 1.0000x reference)
#include <cuda_runtime.h>
#include <cuda_bf16.h>
#include <math.h>

// Problem constants
#define BB 64
#define NN 128
#define DLAT 80
#define NH 8
#define DH 64
#define INNER 512
#define FFD 160
#define MHD 20
#define DEPTH 24
#define ROWS (BB * NN)   // 8192

// ---------------------------------------------------------------------------
// Scratch (device globals; no allocation allowed)
// ---------------------------------------------------------------------------
__device__ float g_x[ROWS * DLAT];          // residual stream
__device__ float g_qkv[ROWS * 3 * INNER];   // fused Q|K|V (row stride 1536)
__device__ float g_o[ROWS * INNER];         // attention output
__device__ float g_f[ROWS * FFD];           // FF hidden
__device__ float g_bias[BB * NN * NN];      // graph attention bias

// ---------------------------------------------------------------------------
// helpers
// ---------------------------------------------------------------------------
__device__ __forceinline__ float to_tf32(float x)
{
    float r;
    asm("cvt.rna.tf32.f32 %0, %1;" : "=f"(r) : "f"(x));
    return r;
}

__device__ __forceinline__ void mma_tf32(float* c, const float* a, const float* b)
{
    asm volatile(
        "mma.sync.aligned.m16n8k8.row.col.f32.tf32.tf32.f32 "
        "{%0,%1,%2,%3}, {%4,%5,%6,%7}, {%8,%9}, {%0,%1,%2,%3};"
        : "+f"(c[0]), "+f"(c[1]), "+f"(c[2]), "+f"(c[3])
        : "r"(__float_as_uint(a[0])), "r"(__float_as_uint(a[1])),
          "r"(__float_as_uint(a[2])), "r"(__float_as_uint(a[3])),
          "r"(__float_as_uint(b[0])), "r"(__float_as_uint(b[1])));
}

__device__ __forceinline__ void mma_bf16(float* c, const unsigned* a, const unsigned* b)
{
    asm volatile(
        "mma.sync.aligned.m16n8k16.row.col.f32.bf16.bf16.f32 "
        "{%0,%1,%2,%3}, {%4,%5,%6,%7}, {%8,%9}, {%0,%1,%2,%3};"
        : "+f"(c[0]), "+f"(c[1]), "+f"(c[2]), "+f"(c[3])
        : "r"(a[0]), "r"(a[1]), "r"(a[2]), "r"(a[3]),
          "r"(b[0]), "r"(b[1]));
}

// ---------------------------------------------------------------------------
// Graph bias
// ---------------------------------------------------------------------------
__global__ void bias_kernel(const int* __restrict__ spatial_pos,
                            const int* __restrict__ edge_input,
                            const float* __restrict__ edge_emb,
                            const float* __restrict__ edge_dis_w,
                            const float* __restrict__ spatial_emb,
                            float* __restrict__ bias)
{
    __shared__ float s_edge[64];
    __shared__ float s_w[MHD];
    __shared__ float s_sp[40];
    int t = threadIdx.x;               // 128 threads
    if (t < 64) s_edge[t] = edge_emb[t];
    if (t < MHD) s_w[t] = edge_dis_w[t];
    if (t >= 64 && t < 104) s_sp[t - 64] = spatial_emb[t - 64];
    __syncthreads();

    long bi = blockIdx.x;              // b*N + i
    int j = t;
    const int* ei = edge_input + (bi * NN + j) * (MHD * 3);
    float acc = 0.f;
#pragma unroll
    for (int hh = 0; hh < MHD; hh++) {
        float e = (s_edge[ei[hh * 3 + 0]] + s_edge[ei[hh * 3 + 1]] +
                   s_edge[ei[hh * 3 + 2]]) * (1.f / 3.f);
        acc += e * s_w[hh];
    }
    int sp0 = spatial_pos[bi * NN + j];
    int sp = (sp0 == 0) ? 1 : sp0;
    sp = (sp > 1) ? sp - 1 : sp;
    sp = min(sp, MHD);
    bias[bi * NN + j] = acc / (float)sp + s_sp[sp0];
}

// ---------------------------------------------------------------------------
// Node embedding
// ---------------------------------------------------------------------------
__global__ void embed_kernel(const int* __restrict__ x_nodes,
                             const int* __restrict__ indeg,
                             const int* __restrict__ outdeg,
                             const float* __restrict__ atom_emb,
                             const float* __restrict__ indeg_emb,
                             const float* __restrict__ outdeg_emb,
                             float* __restrict__ x)
{
    int r = blockIdx.x;      // 8192 rows
    int d = threadIdx.x;     // 80
    int a = x_nodes[r], i = indeg[r], o = outdeg[r];
    x[(long)r * DLAT + d] = atom_emb[a * DLAT + d] + indeg_emb[i * DLAT + d]
                          + outdeg_emb[o * DLAT + d];
}

// ---------------------------------------------------------------------------
// Panel GEMM with fused LayerNorm (K = DLAT = 80 only).
//   EPI 0: plain store     EPI 2: gelu_exact(acc + bias[n])
// ---------------------------------------------------------------------------
#define PAST 84
#define PANEL_SMEM ((128 + 64) * PAST * 4)   // 64512 bytes

template <int EPI>
__global__ void __launch_bounds__(256) panel_gemm(
    const float* __restrict__ X,
    const float* __restrict__ lng, const float* __restrict__ lnb,
    const float* __restrict__ Wa, const float* __restrict__ Wb,
    int NcA, int NcB,
    const float* __restrict__ bias,
    float* __restrict__ C, int ldc)
{
    extern __shared__ float sm[];
    float* As = sm;                // [128][84]
    float* Bs = sm + 128 * PAST;   // [64][84]

    int bm = blockIdx.y * 128;
    int n_glob = blockIdx.x * 64;
    const float* W; int Wn; int wcol;
    if (n_glob < NcA) { W = Wa; Wn = NcA; wcol = n_glob; }
    else             { W = Wb; Wn = NcB; wcol = n_glob - NcA; }
    int NcTot = NcA + NcB;

    int t = threadIdx.x;

    {   // A panel: load 128x80, fused LayerNorm, tf32 store
        int r = t >> 1, half = t & 1;
        const float* ar = X + (long)(bm + r) * DLAT + half * 40;
        float* ad = As + r * PAST + half * 40;
        float s = 0.f;
#pragma unroll
        for (int i = 0; i < 40; i += 4) {
            float4 a4 = *(const float4*)(ar + i);
            *(float4*)(ad + i) = a4;
            s += (a4.x + a4.y) + (a4.z + a4.w);
        }
        s += __shfl_xor_sync(0xffffffffu, s, 1);
        float mean = s * (1.f / DLAT);
        float vs = 0.f;
#pragma unroll
        for (int i = 0; i < 40; i++) { float d = ad[i] - mean; vs += d * d; }
        vs += __shfl_xor_sync(0xffffffffu, vs, 1);
        float inv = rsqrtf(vs * (1.f / DLAT) + 1e-5f);
        const float* gg = lng + half * 40;
        const float* bb = lnb + half * 40;
#pragma unroll
        for (int i = 0; i < 40; i++)
            ad[i] = to_tf32((ad[i] - mean) * inv * gg[i] + bb[i]);
    }

    {   // B panel: transpose-stage W[k][wcol+n] -> Bs[n][k] (tf32)
        int kr = t >> 4;          // 0..15
        int n0 = (t & 15) * 4;    // 0..60
#pragma unroll
        for (int kb = 0; kb < DLAT; kb += 16) {
            int k = kb + kr;
            float4 w4 = make_float4(0.f, 0.f, 0.f, 0.f);
            if (wcol + n0 < Wn) {
                const float* wp = W + (long)k * Wn + wcol + n0;
                if (wcol + n0 + 3 < Wn) {
                    w4 = *(const float4*)wp;
                } else {
                    w4.x = wp[0];
                    if (wcol + n0 + 1 < Wn) w4.y = wp[1];
                    if (wcol + n0 + 2 < Wn) w4.z = wp[2];
                }
            }
            Bs[(n0 + 0) * PAST + k] = to_tf32(w4.x);
            Bs[(n0 + 1) * PAST + k] = to_tf32(w4.y);
            Bs[(n0 + 2) * PAST + k] = to_tf32(w4.z);
            Bs[(n0 + 3) * PAST + k] = to_tf32(w4.w);
        }
    }
    __syncthreads();

    int warp = t >> 5, lane = t & 31;
    int g = lane >> 2, tig = lane & 3;
    int warpM = warp >> 1, warpN = warp & 1;

    float acc[2][4][4] = {};

#pragma unroll
    for (int kt = 0; kt < 10; kt++) {
        int kk = kt * 8;
        float af[2][4];
#pragma unroll
        for (int mt = 0; mt < 2; mt++) {
            int r = warpM * 32 + mt * 16;
            af[mt][0] = As[(r + g) * PAST + kk + tig];
            af[mt][1] = As[(r + g + 8) * PAST + kk + tig];
            af[mt][2] = As[(r + g) * PAST + kk + tig + 4];
            af[mt][3] = As[(r + g + 8) * PAST + kk + tig + 4];
        }
#pragma unroll
        for (int nt = 0; nt < 4; nt++) {
            float bf[2];
            int n = warpN * 32 + nt * 8 + g;
            bf[0] = Bs[n * PAST + kk + tig];
            bf[1] = Bs[n * PAST + kk + tig + 4];
#pragma unroll
            for (int mt = 0; mt < 2; mt++)
                mma_tf32(acc[mt][nt], af[mt], bf);
        }
    }

#pragma unroll
    for (int mt = 0; mt < 2; mt++) {
        long rL = bm + warpM * 32 + mt * 16 + g;
        long rH = rL + 8;
#pragma unroll
        for (int nt = 0; nt < 4; nt++) {
            int n = n_glob + warpN * 32 + nt * 8 + 2 * tig;
            if (n >= NcTot) continue;
            float v0 = acc[mt][nt][0], v1 = acc[mt][nt][1];
            float v2 = acc[mt][nt][2], v3 = acc[mt][nt][3];
            if (EPI == 2) {
                float b0 = bias[n], b1 = bias[n + 1];
                v0 += b0; v1 += b1; v2 += b0; v3 += b1;
                v0 = 0.5f * v0 * (1.f + erff(v0 * 0.70710678118654752f));
                v1 = 0.5f * v1 * (1.f + erff(v1 * 0.70710678118654752f));
                v2 = 0.5f * v2 * (1.f + erff(v2 * 0.70710678118654752f));
                v3 = 0.5f * v3 * (1.f + erff(v3 * 0.70710678118654752f));
            }
            float2 w0, w1;
            w0.x = v0; w0.y = v1;
            w1.x = v2; w1.y = v3;
            *(float2*)&C[rL * ldc + n] = w0;
            *(float2*)&C[rH * ldc + n] = w1;
        }
    }
}

// ---------------------------------------------------------------------------
// Chunked tf32 GEMM for Wo (K=512) and FF2 (K=160). BM=64 (R7 win).
//   EPI 1: +bias[n]+res[m,n]
// ---------------------------------------------------------------------------
#define GBM 64
#define GBN 64
#define GBK 16
#define GAS 20
#define GBS 20

template <int EPI>
__global__ void __launch_bounds__(256) mma_gemm(
    const float* __restrict__ A, const float* __restrict__ W,
    const float* __restrict__ bias, const float* __restrict__ res,
    float* __restrict__ C, int M, int K, int Nc, int ldc, int coff)
{
    __shared__ float As[GBM * GAS];
    __shared__ float Bs[GBN * GBS];
    int bm = blockIdx.y * GBM;
    int bn = blockIdx.x * GBN;
    int tid = threadIdx.x;
    int warp = tid >> 5, lane = tid & 31;
    int g = lane >> 2, tig = lane & 3;
    int warpM = warp >> 2, warpN = warp & 3;

    float acc[2][2][4] = {};

    for (int k0 = 0; k0 < K; k0 += GBK) {
        {
            int m = tid >> 2;
            int kq = (tid & 3) * 4;
            float4 a4 = *(const float4*)(A + (long)(bm + m) * K + k0 + kq);
            float* ad = As + m * GAS + kq;
            ad[0] = to_tf32(a4.x); ad[1] = to_tf32(a4.y);
            ad[2] = to_tf32(a4.z); ad[3] = to_tf32(a4.w);
        }
        {
            int kr = tid >> 4;
            int n0 = (tid & 15) * 4;
            const float* wp = W + (long)(k0 + kr) * Nc + bn + n0;
            float4 w4 = make_float4(0.f, 0.f, 0.f, 0.f);
            if (bn + n0 + 3 < Nc) {
                w4 = *(const float4*)wp;
            } else if (bn + n0 < Nc) {
                w4.x = wp[0];
                if (bn + n0 + 1 < Nc) w4.y = wp[1];
                if (bn + n0 + 2 < Nc) w4.z = wp[2];
            }
            Bs[(n0 + 0) * GBS + kr] = to_tf32(w4.x);
            Bs[(n0 + 1) * GBS + kr] = to_tf32(w4.y);
            Bs[(n0 + 2) * GBS + kr] = to_tf32(w4.z);
            Bs[(n0 + 3) * GBS + kr] = to_tf32(w4.w);
        }
        __syncthreads();
#pragma unroll
        for (int kt = 0; kt < 2; kt++) {
            int kk = kt * 8;
            float af[2][4];
#pragma unroll
            for (int mt = 0; mt < 2; mt++) {
                int r = warpM * 32 + mt * 16;
                af[mt][0] = As[(r + g) * GAS + kk + tig];
                af[mt][1] = As[(r + g + 8) * GAS + kk + tig];
                af[mt][2] = As[(r + g) * GAS + kk + tig + 4];
                af[mt][3] = As[(r + g + 8) * GAS + kk + tig + 4];
            }
#pragma unroll
            for (int nt = 0; nt < 2; nt++) {
                float bf[2];
                int n = warpN * 16 + nt * 8 + g;
                bf[0] = Bs[n * GBS + kk + tig];
                bf[1] = Bs[n * GBS + kk + tig + 4];
#pragma unroll
                for (int mt = 0; mt < 2; mt++)
                    mma_tf32(acc[mt][nt], af[mt], bf);
            }
        }
        __syncthreads();
    }

#pragma unroll
    for (int mt = 0; mt < 2; mt++) {
        long rL = bm + warpM * 32 + mt * 16 + g;
        long rH = rL + 8;
#pragma unroll
        for (int nt = 0; nt < 2; nt++) {
            int n = bn + warpN * 16 + nt * 8 + 2 * tig;
            if (n >= Nc) continue;
            float v0 = acc[mt][nt][0], v1 = acc[mt][nt][1];
            float v2 = acc[mt][nt][2], v3 = acc[mt][nt][3];
            if (EPI == 1) {
                float b0 = bias[n], b1 = bias[n + 1];
                const float* rL_p = res + rL * Nc + n;
                const float* rH_p = res + rH * Nc + n;
                v0 += b0 + rL_p[0]; v1 += b1 + rL_p[1];
                v2 += b0 + rH_p[0]; v3 += b1 + rH_p[1];
            }
            float2 w0, w1;
            w0.x = v0; w0.y = v1;
            w1.x = v2; w1.y = v3;
            *(float2*)&C[rL * ldc + coff + n] = w0;
            *(float2*)&C[rH * ldc + coff + n] = w1;
        }
    }
}

// ---------------------------------------------------------------------------
// bf16 flash attention, register-direct P (NO P smem round trip).
// The PV A-fragment cols (kt*16+2*tig) equal the QK C-fragment cols
// (nt*8+2*tig for nt=2kt,2kt+1) for the SAME lane -> P packs stay in regs.
// Numerics bit-identical to the R9 smem version (same bf16 values, same
// mma/accumulation order, same fp32 sums).
// Smem: Ks[64][72] + Vt[64][72] + Qs[128][72] (bf16) = 36864 B -> 2 blocks/SM.
// ---------------------------------------------------------------------------
#define AKB 72
#define ATTN_SMEM ((64 + 64 + 128) * AKB * 2)   // 36864 bytes

__global__ void __launch_bounds__(256, 2) attn_kernel(
    const float* __restrict__ qkv, const float* __restrict__ bias,
    float* __restrict__ o)
{
    extern __shared__ float sm[];
    __nv_bfloat16* Ks = (__nv_bfloat16*)sm;        // [64][72]  K chunk (rows j)
    __nv_bfloat16* Vt = Ks + 64 * AKB;             // [64][72]  V chunk (rows d, cols j)
    __nv_bfloat16* Qs = Vt + 64 * AKB;             // [128][72] Q staging

    int bh = blockIdx.x;
    int b = bh >> 3, h = bh & 7;
    int t = threadIdx.x;

    // Stage Q (bf16)
    {
        int r = t >> 1, half = t & 1;
        const float* qr = qkv + ((long)(b * NN + r)) * 1536 + h * DH + half * 32;
        __nv_bfloat16* qd = Qs + r * AKB + half * 32;
#pragma unroll
        for (int i = 0; i < 32; i += 4) {
            float4 q4 = *(const float4*)(qr + i);
            *(__nv_bfloat162*)(qd + i)     = __floats2bfloat162_rn(q4.x, q4.y);
            *(__nv_bfloat162*)(qd + i + 2) = __floats2bfloat162_rn(q4.z, q4.w);
        }
    }
    __syncthreads();

    int warp = t >> 5, lane = t & 31;
    int g = lane >> 2, tig = lane & 3;
    int m0 = warp * 16;
    int rowL = m0 + g, rowH = m0 + g + 8;

    // Q fragments (bf16 m16n8k16 A-layout), persistent
    unsigned qa[4][4];
#pragma unroll
    for (int kt = 0; kt < 4; kt++) {
        int k2 = kt * 16 + 2 * tig;
        qa[kt][0] = *(const unsigned*)(Qs + rowL * AKB + k2);
        qa[kt][1] = *(const unsigned*)(Qs + rowH * AKB + k2);
        qa[kt][2] = *(const unsigned*)(Qs + rowL * AKB + k2 + 8);
        qa[kt][3] = *(const unsigned*)(Qs + rowH * AKB + k2 + 8);
    }

    float mr0 = -1e30f, mr1 = -1e30f, sum0 = 0.f, sum1 = 0.f;
    float oacc[8][4] = {};

#pragma unroll
    for (int jc = 0; jc < 2; jc++) {
        int j0 = jc * 64;
        __syncthreads();   // K/V chunk reuse fence
        {   // load K rows (bf16) + V transposed (bf16): rows j0..j0+63
            int r2 = t >> 2;              // local j 0..63
            int q4o = (t & 3) * 16;       // d base
            const float* kr = qkv + ((long)(b * NN + j0 + r2)) * 1536 + 512
                              + h * DH + q4o;
            const float* vr = kr + 512;
            __nv_bfloat16* kd = Ks + r2 * AKB + q4o;
#pragma unroll
            for (int i = 0; i < 16; i += 4) {
                float4 k4 = *(const float4*)(kr + i);
                float4 v4 = *(const float4*)(vr + i);
                *(__nv_bfloat162*)(kd + i)     = __floats2bfloat162_rn(k4.x, k4.y);
                *(__nv_bfloat162*)(kd + i + 2) = __floats2bfloat162_rn(k4.z, k4.w);
                Vt[(q4o + i + 0) * AKB + r2] = __float2bfloat16_rn(v4.x);
                Vt[(q4o + i + 1) * AKB + r2] = __float2bfloat16_rn(v4.y);
                Vt[(q4o + i + 2) * AKB + r2] = __float2bfloat16_rn(v4.z);
                Vt[(q4o + i + 3) * AKB + r2] = __float2bfloat16_rn(v4.w);
            }
        }
        __syncthreads();

        // S chunk = Q @ K_chunk^T  (4 k-tiles of 16, 8 n-tiles of 8)
        float sacc[8][4] = {};
#pragma unroll
        for (int kt = 0; kt < 4; kt++) {
#pragma unroll
            for (int nt = 0; nt < 8; nt++) {
                unsigned bfr[2];
                const __nv_bfloat16* kp = Ks + (nt * 8 + g) * AKB + kt * 16 + 2 * tig;
                bfr[0] = *(const unsigned*)kp;
                bfr[1] = *(const unsigned*)(kp + 8);
                mma_bf16(sacc[nt], qa[kt], bfr);
            }
        }

        // scale + bias + chunk max
        const float* bL = bias + ((long)b * NN + rowL) * NN + j0 + 2 * tig;
        const float* bH = bias + ((long)b * NN + rowH) * NN + j0 + 2 * tig;
        float cm0 = -1e30f, cm1 = -1e30f;
#pragma unroll
        for (int nt = 0; nt < 8; nt++) {
            float2 b0 = *(const float2*)(bL + nt * 8);
            float2 b1 = *(const float2*)(bH + nt * 8);
            sacc[nt][0] = sacc[nt][0] * 0.125f + b0.x;
            sacc[nt][1] = sacc[nt][1] * 0.125f + b0.y;
            sacc[nt][2] = sacc[nt][2] * 0.125f + b1.x;
            sacc[nt][3] = sacc[nt][3] * 0.125f + b1.y;
            cm0 = fmaxf(cm0, fmaxf(sacc[nt][0], sacc[nt][1]));
            cm1 = fmaxf(cm1, fmaxf(sacc[nt][2], sacc[nt][3]));
        }
        cm0 = fmaxf(cm0, __shfl_xor_sync(0xffffffffu, cm0, 1));
        cm0 = fmaxf(cm0, __shfl_xor_sync(0xffffffffu, cm0, 2));
        cm1 = fmaxf(cm1, __shfl_xor_sync(0xffffffffu, cm1, 1));
        cm1 = fmaxf(cm1, __shfl_xor_sync(0xffffffffu, cm1, 2));

        float mn0 = fmaxf(mr0, cm0), mn1 = fmaxf(mr1, cm1);
        float c0 = __expf(mr0 - mn0), c1 = __expf(mr1 - mn1);
        mr0 = mn0; mr1 = mn1;
        sum0 *= c0; sum1 *= c1;
#pragma unroll
        for (int nt = 0; nt < 8; nt++) {
            oacc[nt][0] *= c0; oacc[nt][1] *= c0;
            oacc[nt][2] *= c1; oacc[nt][3] *= c1;
        }

        // exp + register-direct P packs + O += P @ V (per kt-pair)
#pragma unroll
        for (int kt = 0; kt < 4; kt++) {
            unsigned pa[4];
#pragma unroll
            for (int s = 0; s < 2; s++) {       // nt = 2*kt + s
                int nt = 2 * kt + s;
                float p0 = __expf(sacc[nt][0] - mr0);
                float p1 = __expf(sacc[nt][1] - mr0);
                float p2 = __expf(sacc[nt][2] - mr1);
                float p3 = __expf(sacc[nt][3] - mr1);
                sum0 += p0 + p1;
                sum1 += p2 + p3;
                __nv_bfloat162 tL = __floats2bfloat162_rn(p0, p1);
                __nv_bfloat162 tH = __floats2bfloat162_rn(p2, p3);
                pa[2 * s]     = *(unsigned*)&tL;   // rowL pair
                pa[2 * s + 1] = *(unsigned*)&tH;   // rowH pair
            }
            // A-frag order: a0=rowL(k2), a1=rowH(k2), a2=rowL(k2+8), a3=rowH(k2+8)
            unsigned paf[4];
            paf[0] = pa[0]; paf[1] = pa[1]; paf[2] = pa[2]; paf[3] = pa[3];
            int k2 = kt * 16 + 2 * tig;
#pragma unroll
            for (int nt = 0; nt < 8; nt++) {
                unsigned bfr[2];
                const __nv_bfloat16* vp = Vt + (nt * 8 + g) * AKB + k2;
                bfr[0] = *(const unsigned*)vp;
                bfr[1] = *(const unsigned*)(vp + 8);
                mma_bf16(oacc[nt], paf, bfr);
            }
        }
    }

    // Cross-lane reduction of row sums
    sum0 += __shfl_xor_sync(0xffffffffu, sum0, 1);
    sum0 += __shfl_xor_sync(0xffffffffu, sum0, 2);
    sum1 += __shfl_xor_sync(0xffffffffu, sum1, 1);
    sum1 += __shfl_xor_sync(0xffffffffu, sum1, 2);

    float inv0 = 1.f / sum0, inv1 = 1.f / sum1;
    float* oL = o + ((long)(b * NN + rowL)) * INNER + h * DH;
    float* oH = o + ((long)(b * NN + rowH)) * INNER + h * DH;
#pragma unroll
    for (int nt = 0; nt < 8; nt++) {
        int c = nt * 8 + 2 * tig;
        float2 w0, w1;
        w0.x = oacc[nt][0] * inv0; w0.y = oacc[nt][1] * inv0;
        w1.x = oacc[nt][2] * inv1; w1.y = oacc[nt][3] * inv1;
        *(float2*)&oL[c] = w0;
        *(float2*)&oH[c] = w1;
    }
}

// ---------------------------------------------------------------------------
// Head: mean-pool over N, LayerNorm, dot with Wf
// ---------------------------------------------------------------------------
__global__ void head_kernel(const float* __restrict__ x, const float* __restrict__ g,
                            const float* __restrict__ be, const float* __restrict__ Wf,
                            const float* __restrict__ bf, float* __restrict__ out)
{
    __shared__ float pool[DLAT];
    int b = blockIdx.x;
    int t = threadIdx.x;     // 128 threads
    if (t < DLAT) {
        float s = 0.f;
        const float* xb = x + (long)b * NN * DLAT + t;
        for (int n = 0; n < NN; n++) s += xb[n * DLAT];
        pool[t] = s * (1.f / NN);
    }
    __syncthreads();
    if (t < 32) {
        float v0 = pool[t], v1 = pool[t + 32];
        float v2 = (t + 64 < DLAT) ? pool[t + 64] : 0.f;
        float s = v0 + v1 + v2;
#pragma unroll
        for (int o = 16; o; o >>= 1) s += __shfl_xor_sync(0xffffffffu, s, o);
        float mean = s * (1.f / DLAT);
        float d0 = v0 - mean, d1 = v1 - mean;
        float d2 = (t + 64 < DLAT) ? (v2 - mean) : 0.f;
        float vs = d0 * d0 + d1 * d1 + d2 * d2;
#pragma unroll
        for (int o = 16; o; o >>= 1) vs += __shfl_xor_sync(0xffffffffu, vs, o);
        float inv = rsqrtf(vs * (1.f / DLAT) + 1e-5f);
        float dot = (d0 * inv * g[t] + be[t]) * Wf[t]
                  + (d1 * inv * g[t + 32] + be[t + 32]) * Wf[t + 32];
        if (t + 64 < DLAT)
            dot += (d2 * inv * g[t + 64] + be[t + 64]) * Wf[t + 64];
#pragma unroll
        for (int o = 16; o; o >>= 1) dot += __shfl_xor_sync(0xffffffffu, dot, o);
        if (t == 0) out[b] = dot + bf[0];
    }
}

// ---------------------------------------------------------------------------
// Launch
// ---------------------------------------------------------------------------
extern "C" void kernel_launch(void* const* d_in, const int* in_sizes, int n_in,
                              void* d_out, int out_size)
{
    const int*   spatial_pos = (const int*)d_in[0];
    const int*   edge_input  = (const int*)d_in[1];
    const int*   x_nodes     = (const int*)d_in[2];
    const int*   indeg       = (const int*)d_in[3];
    const int*   outdeg      = (const int*)d_in[4];
    const float* atom_emb    = (const float*)d_in[5];
    const float* indeg_emb   = (const float*)d_in[6];
    const float* outdeg_emb  = (const float*)d_in[7];
    const float* edge_emb    = (const float*)d_in[8];
    const float* edge_dis_w  = (const float*)d_in[9];
    const float* spatial_emb = (const float*)d_in[10];
    const float* ln1_g = (const float*)d_in[11];
    const float* ln1_b = (const float*)d_in[12];
    const float* Wq    = (const float*)d_in[13];
    const float* Wkv   = (const float*)d_in[14];
    const float* Wo    = (const float*)d_in[15];
    const float* bo    = (const float*)d_in[16];
    const float* ln2_g = (const float*)d_in[17];
    const float* ln2_b = (const float*)d_in[18];
    const float* W1    = (const float*)d_in[19];
    const float* b1    = (const float*)d_in[20];
    const float* W2    = (const float*)d_in[21];
    const float* b2    = (const float*)d_in[22];
    const float* lnf_g = (const float*)d_in[23];
    const float* lnf_b = (const float*)d_in[24];
    const float* Wf    = (const float*)d_in[25];
    const float* bf    = (const float*)d_in[26];
    float* out = (float*)d_out;

    float *gx, *gqkv, *go, *gf, *gb;
    cudaGetSymbolAddress((void**)&gx,   g_x);
    cudaGetSymbolAddress((void**)&gqkv, g_qkv);
    cudaGetSymbolAddress((void**)&go,   g_o);
    cudaGetSymbolAddress((void**)&gf,   g_f);
    cudaGetSymbolAddress((void**)&gb,   g_bias);

    cudaFuncSetAttribute(attn_kernel,
                         cudaFuncAttributeMaxDynamicSharedMemorySize, ATTN_SMEM);
    cudaFuncSetAttribute(panel_gemm<0>,
                         cudaFuncAttributeMaxDynamicSharedMemorySize, PANEL_SMEM);
    cudaFuncSetAttribute(panel_gemm<2>,
                         cudaFuncAttributeMaxDynamicSharedMemorySize, PANEL_SMEM);

    bias_kernel<<<BB * NN, 128>>>(spatial_pos, edge_input, edge_emb,
                                  edge_dis_w, spatial_emb, gb);
    embed_kernel<<<ROWS, DLAT>>>(x_nodes, indeg, outdeg,
                                 atom_emb, indeg_emb, outdeg_emb, gx);

    for (int l = 0; l < DEPTH; l++) {
        panel_gemm<0><<<dim3(24, ROWS / 128), 256, PANEL_SMEM>>>(
            gx, ln1_g + l * DLAT, ln1_b + l * DLAT,
            Wq + (long)l * DLAT * INNER, Wkv + (long)l * DLAT * 2 * INNER,
            INNER, 2 * INNER, nullptr, gqkv, 3 * INNER);
        attn_kernel<<<BB * NH, 256, ATTN_SMEM>>>(gqkv, gb, go);
        mma_gemm<1><<<dim3(2, ROWS / GBM), 256>>>(
            go, Wo + (long)l * INNER * DLAT, bo + l * DLAT, gx,
            gx, ROWS, INNER, DLAT, DLAT, 0);
        panel_gemm<2><<<dim3(3, ROWS / 128), 256, PANEL_SMEM>>>(
            gx, ln2_g + l * DLAT, ln2_b + l * DLAT,
            W1 + (long)l * DLAT * FFD, nullptr,
            FFD, 0, b1 + l * FFD, gf, FFD);
        mma_gemm<1><<<dim3(2, ROWS / GBM), 256>>>(
            gf, W2 + (long)l * FFD * DLAT, b2 + l * DLAT, gx,
            gx, ROWS, FFD, DLAT, DLAT, 0);
    }

    head_kernel<<<BB, 128>>>(gx, lnf_g, lnf_b, Wf, bf, out);
}

// round 13
// speedup vs baseline: 1.0593x; 1.0593x over previous
#include <cuda_runtime.h>
#include <cuda_bf16.h>
#include <math.h>

// Problem constants
#define BB 64
#define NN 128
#define DLAT 80
#define NH 8
#define DH 64
#define INNER 512
#define FFD 160
#define MHD 20
#define DEPTH 24
#define ROWS (BB * NN)   // 8192

// ---------------------------------------------------------------------------
// Scratch (device globals; no allocation allowed)
// ---------------------------------------------------------------------------
__device__ float g_x[ROWS * DLAT];                  // residual stream
__device__ __nv_bfloat16 g_qkv[ROWS * 3 * INNER];   // fused Q|K|V (bf16, stride 1536)
__device__ float g_o[ROWS * INNER];                 // attention output
__device__ float g_f[ROWS * FFD];                   // FF hidden
__device__ float g_bias[BB * NN * NN];              // graph attention bias

// ---------------------------------------------------------------------------
// helpers
// ---------------------------------------------------------------------------
__device__ __forceinline__ float to_tf32(float x)
{
    float r;
    asm("cvt.rna.tf32.f32 %0, %1;" : "=f"(r) : "f"(x));
    return r;
}

__device__ __forceinline__ void mma_tf32(float* c, const float* a, const float* b)
{
    asm volatile(
        "mma.sync.aligned.m16n8k8.row.col.f32.tf32.tf32.f32 "
        "{%0,%1,%2,%3}, {%4,%5,%6,%7}, {%8,%9}, {%0,%1,%2,%3};"
        : "+f"(c[0]), "+f"(c[1]), "+f"(c[2]), "+f"(c[3])
        : "r"(__float_as_uint(a[0])), "r"(__float_as_uint(a[1])),
          "r"(__float_as_uint(a[2])), "r"(__float_as_uint(a[3])),
          "r"(__float_as_uint(b[0])), "r"(__float_as_uint(b[1])));
}

__device__ __forceinline__ void mma_bf16(float* c, const unsigned* a, const unsigned* b)
{
    asm volatile(
        "mma.sync.aligned.m16n8k16.row.col.f32.bf16.bf16.f32 "
        "{%0,%1,%2,%3}, {%4,%5,%6,%7}, {%8,%9}, {%0,%1,%2,%3};"
        : "+f"(c[0]), "+f"(c[1]), "+f"(c[2]), "+f"(c[3])
        : "r"(a[0]), "r"(a[1]), "r"(a[2]), "r"(a[3]),
          "r"(b[0]), "r"(b[1]));
}

// ---------------------------------------------------------------------------
// Graph bias
// ---------------------------------------------------------------------------
__global__ void bias_kernel(const int* __restrict__ spatial_pos,
                            const int* __restrict__ edge_input,
                            const float* __restrict__ edge_emb,
                            const float* __restrict__ edge_dis_w,
                            const float* __restrict__ spatial_emb,
                            float* __restrict__ bias)
{
    __shared__ float s_edge[64];
    __shared__ float s_w[MHD];
    __shared__ float s_sp[40];
    int t = threadIdx.x;               // 128 threads
    if (t < 64) s_edge[t] = edge_emb[t];
    if (t < MHD) s_w[t] = edge_dis_w[t];
    if (t >= 64 && t < 104) s_sp[t - 64] = spatial_emb[t - 64];
    __syncthreads();

    long bi = blockIdx.x;              // b*N + i
    int j = t;
    const int* ei = edge_input + (bi * NN + j) * (MHD * 3);
    float acc = 0.f;
#pragma unroll
    for (int hh = 0; hh < MHD; hh++) {
        float e = (s_edge[ei[hh * 3 + 0]] + s_edge[ei[hh * 3 + 1]] +
                   s_edge[ei[hh * 3 + 2]]) * (1.f / 3.f);
        acc += e * s_w[hh];
    }
    int sp0 = spatial_pos[bi * NN + j];
    int sp = (sp0 == 0) ? 1 : sp0;
    sp = (sp > 1) ? sp - 1 : sp;
    sp = min(sp, MHD);
    bias[bi * NN + j] = acc / (float)sp + s_sp[sp0];
}

// ---------------------------------------------------------------------------
// Node embedding
// ---------------------------------------------------------------------------
__global__ void embed_kernel(const int* __restrict__ x_nodes,
                             const int* __restrict__ indeg,
                             const int* __restrict__ outdeg,
                             const float* __restrict__ atom_emb,
                             const float* __restrict__ indeg_emb,
                             const float* __restrict__ outdeg_emb,
                             float* __restrict__ x)
{
    int r = blockIdx.x;      // 8192 rows
    int d = threadIdx.x;     // 80
    int a = x_nodes[r], i = indeg[r], o = outdeg[r];
    x[(long)r * DLAT + d] = atom_emb[a * DLAT + d] + indeg_emb[i * DLAT + d]
                          + outdeg_emb[o * DLAT + d];
}

// ---------------------------------------------------------------------------
// Panel GEMM with fused LayerNorm (K = DLAT = 80 only).
//   EPI 0: store bf16 (QKV path; identical rounding to prior attn-side cvt)
//   EPI 2: gelu_exact(acc + bias[n]), fp32 store
// ---------------------------------------------------------------------------
#define PAST 84
#define PANEL_SMEM ((128 + 64) * PAST * 4)   // 64512 bytes

template <int EPI>
__global__ void __launch_bounds__(256) panel_gemm(
    const float* __restrict__ X,
    const float* __restrict__ lng, const float* __restrict__ lnb,
    const float* __restrict__ Wa, const float* __restrict__ Wb,
    int NcA, int NcB,
    const float* __restrict__ bias,
    void* __restrict__ Cout, int ldc)
{
    extern __shared__ float sm[];
    float* As = sm;                // [128][84]
    float* Bs = sm + 128 * PAST;   // [64][84]

    int bm = blockIdx.y * 128;
    int n_glob = blockIdx.x * 64;
    const float* W; int Wn; int wcol;
    if (n_glob < NcA) { W = Wa; Wn = NcA; wcol = n_glob; }
    else             { W = Wb; Wn = NcB; wcol = n_glob - NcA; }
    int NcTot = NcA + NcB;

    int t = threadIdx.x;

    {   // A panel: load 128x80, fused LayerNorm, tf32 store
        int r = t >> 1, half = t & 1;
        const float* ar = X + (long)(bm + r) * DLAT + half * 40;
        float* ad = As + r * PAST + half * 40;
        float s = 0.f;
#pragma unroll
        for (int i = 0; i < 40; i += 4) {
            float4 a4 = *(const float4*)(ar + i);
            *(float4*)(ad + i) = a4;
            s += (a4.x + a4.y) + (a4.z + a4.w);
        }
        s += __shfl_xor_sync(0xffffffffu, s, 1);
        float mean = s * (1.f / DLAT);
        float vs = 0.f;
#pragma unroll
        for (int i = 0; i < 40; i++) { float d = ad[i] - mean; vs += d * d; }
        vs += __shfl_xor_sync(0xffffffffu, vs, 1);
        float inv = rsqrtf(vs * (1.f / DLAT) + 1e-5f);
        const float* gg = lng + half * 40;
        const float* bb = lnb + half * 40;
#pragma unroll
        for (int i = 0; i < 40; i++)
            ad[i] = to_tf32((ad[i] - mean) * inv * gg[i] + bb[i]);
    }

    {   // B panel: transpose-stage W[k][wcol+n] -> Bs[n][k] (tf32)
        int kr = t >> 4;          // 0..15
        int n0 = (t & 15) * 4;    // 0..60
#pragma unroll
        for (int kb = 0; kb < DLAT; kb += 16) {
            int k = kb + kr;
            float4 w4 = make_float4(0.f, 0.f, 0.f, 0.f);
            if (wcol + n0 < Wn) {
                const float* wp = W + (long)k * Wn + wcol + n0;
                if (wcol + n0 + 3 < Wn) {
                    w4 = *(const float4*)wp;
                } else {
                    w4.x = wp[0];
                    if (wcol + n0 + 1 < Wn) w4.y = wp[1];
                    if (wcol + n0 + 2 < Wn) w4.z = wp[2];
                }
            }
            Bs[(n0 + 0) * PAST + k] = to_tf32(w4.x);
            Bs[(n0 + 1) * PAST + k] = to_tf32(w4.y);
            Bs[(n0 + 2) * PAST + k] = to_tf32(w4.z);
            Bs[(n0 + 3) * PAST + k] = to_tf32(w4.w);
        }
    }
    __syncthreads();

    int warp = t >> 5, lane = t & 31;
    int g = lane >> 2, tig = lane & 3;
    int warpM = warp >> 1, warpN = warp & 1;

    float acc[2][4][4] = {};

#pragma unroll
    for (int kt = 0; kt < 10; kt++) {
        int kk = kt * 8;
        float af[2][4];
#pragma unroll
        for (int mt = 0; mt < 2; mt++) {
            int r = warpM * 32 + mt * 16;
            af[mt][0] = As[(r + g) * PAST + kk + tig];
            af[mt][1] = As[(r + g + 8) * PAST + kk + tig];
            af[mt][2] = As[(r + g) * PAST + kk + tig + 4];
            af[mt][3] = As[(r + g + 8) * PAST + kk + tig + 4];
        }
#pragma unroll
        for (int nt = 0; nt < 4; nt++) {
            float bf[2];
            int n = warpN * 32 + nt * 8 + g;
            bf[0] = Bs[n * PAST + kk + tig];
            bf[1] = Bs[n * PAST + kk + tig + 4];
#pragma unroll
            for (int mt = 0; mt < 2; mt++)
                mma_tf32(acc[mt][nt], af[mt], bf);
        }
    }

#pragma unroll
    for (int mt = 0; mt < 2; mt++) {
        long rL = bm + warpM * 32 + mt * 16 + g;
        long rH = rL + 8;
#pragma unroll
        for (int nt = 0; nt < 4; nt++) {
            int n = n_glob + warpN * 32 + nt * 8 + 2 * tig;
            if (n >= NcTot) continue;
            float v0 = acc[mt][nt][0], v1 = acc[mt][nt][1];
            float v2 = acc[mt][nt][2], v3 = acc[mt][nt][3];
            if (EPI == 0) {
                __nv_bfloat16* Cb = (__nv_bfloat16*)Cout;
                *(__nv_bfloat162*)&Cb[rL * ldc + n] = __floats2bfloat162_rn(v0, v1);
                *(__nv_bfloat162*)&Cb[rH * ldc + n] = __floats2bfloat162_rn(v2, v3);
            } else {
                float b0 = bias[n], b1 = bias[n + 1];
                v0 += b0; v1 += b1; v2 += b0; v3 += b1;
                v0 = 0.5f * v0 * (1.f + erff(v0 * 0.70710678118654752f));
                v1 = 0.5f * v1 * (1.f + erff(v1 * 0.70710678118654752f));
                v2 = 0.5f * v2 * (1.f + erff(v2 * 0.70710678118654752f));
                v3 = 0.5f * v3 * (1.f + erff(v3 * 0.70710678118654752f));
                float* Cf = (float*)Cout;
                float2 w0, w1;
                w0.x = v0; w0.y = v1;
                w1.x = v2; w1.y = v3;
                *(float2*)&Cf[rL * ldc + n] = w0;
                *(float2*)&Cf[rH * ldc + n] = w1;
            }
        }
    }
}

// ---------------------------------------------------------------------------
// Chunked tf32 GEMM for Wo (K=512) and FF2 (K=160). BM=64.
//   EPI 1: +bias[n]+res[m,n]
// ---------------------------------------------------------------------------
#define GBM 64
#define GBN 64
#define GBK 16
#define GAS 20
#define GBS 20

template <int EPI>
__global__ void __launch_bounds__(256) mma_gemm(
    const float* __restrict__ A, const float* __restrict__ W,
    const float* __restrict__ bias, const float* __restrict__ res,
    float* __restrict__ C, int M, int K, int Nc, int ldc, int coff)
{
    __shared__ float As[GBM * GAS];
    __shared__ float Bs[GBN * GBS];
    int bm = blockIdx.y * GBM;
    int bn = blockIdx.x * GBN;
    int tid = threadIdx.x;
    int warp = tid >> 5, lane = tid & 31;
    int g = lane >> 2, tig = lane & 3;
    int warpM = warp >> 2, warpN = warp & 3;

    float acc[2][2][4] = {};

    for (int k0 = 0; k0 < K; k0 += GBK) {
        {
            int m = tid >> 2;
            int kq = (tid & 3) * 4;
            float4 a4 = *(const float4*)(A + (long)(bm + m) * K + k0 + kq);
            float* ad = As + m * GAS + kq;
            ad[0] = to_tf32(a4.x); ad[1] = to_tf32(a4.y);
            ad[2] = to_tf32(a4.z); ad[3] = to_tf32(a4.w);
        }
        {
            int kr = tid >> 4;
            int n0 = (tid & 15) * 4;
            const float* wp = W + (long)(k0 + kr) * Nc + bn + n0;
            float4 w4 = make_float4(0.f, 0.f, 0.f, 0.f);
            if (bn + n0 + 3 < Nc) {
                w4 = *(const float4*)wp;
            } else if (bn + n0 < Nc) {
                w4.x = wp[0];
                if (bn + n0 + 1 < Nc) w4.y = wp[1];
                if (bn + n0 + 2 < Nc) w4.z = wp[2];
            }
            Bs[(n0 + 0) * GBS + kr] = to_tf32(w4.x);
            Bs[(n0 + 1) * GBS + kr] = to_tf32(w4.y);
            Bs[(n0 + 2) * GBS + kr] = to_tf32(w4.z);
            Bs[(n0 + 3) * GBS + kr] = to_tf32(w4.w);
        }
        __syncthreads();
#pragma unroll
        for (int kt = 0; kt < 2; kt++) {
            int kk = kt * 8;
            float af[2][4];
#pragma unroll
            for (int mt = 0; mt < 2; mt++) {
                int r = warpM * 32 + mt * 16;
                af[mt][0] = As[(r + g) * GAS + kk + tig];
                af[mt][1] = As[(r + g + 8) * GAS + kk + tig];
                af[mt][2] = As[(r + g) * GAS + kk + tig + 4];
                af[mt][3] = As[(r + g + 8) * GAS + kk + tig + 4];
            }
#pragma unroll
            for (int nt = 0; nt < 2; nt++) {
                float bf[2];
                int n = warpN * 16 + nt * 8 + g;
                bf[0] = Bs[n * GBS + kk + tig];
                bf[1] = Bs[n * GBS + kk + tig + 4];
#pragma unroll
                for (int mt = 0; mt < 2; mt++)
                    mma_tf32(acc[mt][nt], af[mt], bf);
            }
        }
        __syncthreads();
    }

#pragma unroll
    for (int mt = 0; mt < 2; mt++) {
        long rL = bm + warpM * 32 + mt * 16 + g;
        long rH = rL + 8;
#pragma unroll
        for (int nt = 0; nt < 2; nt++) {
            int n = bn + warpN * 16 + nt * 8 + 2 * tig;
            if (n >= Nc) continue;
            float v0 = acc[mt][nt][0], v1 = acc[mt][nt][1];
            float v2 = acc[mt][nt][2], v3 = acc[mt][nt][3];
            if (EPI == 1) {
                float b0 = bias[n], b1 = bias[n + 1];
                const float* rL_p = res + rL * Nc + n;
                const float* rH_p = res + rH * Nc + n;
                v0 += b0 + rL_p[0]; v1 += b1 + rL_p[1];
                v2 += b0 + rH_p[0]; v3 += b1 + rH_p[1];
            }
            float2 w0, w1;
            w0.x = v0; w0.y = v1;
            w1.x = v2; w1.y = v3;
            *(float2*)&C[rL * ldc + coff + n] = w0;
            *(float2*)&C[rH * ldc + coff + n] = w1;
        }
    }
}

// ---------------------------------------------------------------------------
// bf16 flash attention, register-direct P; qkv already bf16 in global.
// Smem: Ks[64][72] + Vt[64][72] + Qs[128][72] (bf16) = 36864 B -> 2 blocks/SM.
// Numerics bit-identical to R11 (same bf16 bits, same mma/accum order).
// ---------------------------------------------------------------------------
#define AKB 72
#define ATTN_SMEM ((64 + 64 + 128) * AKB * 2)   // 36864 bytes

__global__ void __launch_bounds__(256, 2) attn_kernel(
    const __nv_bfloat16* __restrict__ qkv, const float* __restrict__ bias,
    float* __restrict__ o)
{
    extern __shared__ float sm[];
    __nv_bfloat16* Ks = (__nv_bfloat16*)sm;        // [64][72]  K chunk (rows j)
    __nv_bfloat16* Vt = Ks + 64 * AKB;             // [64][72]  V chunk (rows d, cols j)
    __nv_bfloat16* Qs = Vt + 64 * AKB;             // [128][72] Q staging

    int bh = blockIdx.x;
    int b = bh >> 3, h = bh & 7;
    int t = threadIdx.x;

    // Stage Q (already bf16): 32 bf16 = 4 x uint4 per thread
    {
        int r = t >> 1, half = t & 1;
        const __nv_bfloat16* qr = qkv + ((long)(b * NN + r)) * 1536 + h * DH + half * 32;
        __nv_bfloat16* qd = Qs + r * AKB + half * 32;
#pragma unroll
        for (int i = 0; i < 32; i += 8)
            *(uint4*)(qd + i) = *(const uint4*)(qr + i);
    }
    __syncthreads();

    int warp = t >> 5, lane = t & 31;
    int g = lane >> 2, tig = lane & 3;
    int m0 = warp * 16;
    int rowL = m0 + g, rowH = m0 + g + 8;

    // Q fragments (bf16 m16n8k16 A-layout), persistent
    unsigned qa[4][4];
#pragma unroll
    for (int kt = 0; kt < 4; kt++) {
        int k2 = kt * 16 + 2 * tig;
        qa[kt][0] = *(const unsigned*)(Qs + rowL * AKB + k2);
        qa[kt][1] = *(const unsigned*)(Qs + rowH * AKB + k2);
        qa[kt][2] = *(const unsigned*)(Qs + rowL * AKB + k2 + 8);
        qa[kt][3] = *(const unsigned*)(Qs + rowH * AKB + k2 + 8);
    }

    float mr0 = -1e30f, mr1 = -1e30f, sum0 = 0.f, sum1 = 0.f;
    float oacc[8][4] = {};

#pragma unroll
    for (int jc = 0; jc < 2; jc++) {
        int j0 = jc * 64;
        __syncthreads();   // K/V chunk reuse fence
        {   // load K rows + V transposed (bf16 direct)
            int r2 = t >> 2;              // local j 0..63
            int q4o = (t & 3) * 16;       // d base
            const __nv_bfloat16* kr = qkv + ((long)(b * NN + j0 + r2)) * 1536 + 512
                                      + h * DH + q4o;
            const __nv_bfloat16* vr = kr + 512;
            __nv_bfloat16* kd = Ks + r2 * AKB + q4o;
            *(uint4*)(kd)     = *(const uint4*)(kr);
            *(uint4*)(kd + 8) = *(const uint4*)(kr + 8);
            __nv_bfloat16 vbuf[16];
            *(uint4*)(vbuf)     = *(const uint4*)(vr);
            *(uint4*)(vbuf + 8) = *(const uint4*)(vr + 8);
#pragma unroll
            for (int i = 0; i < 16; i++)
                Vt[(q4o + i) * AKB + r2] = vbuf[i];
        }
        __syncthreads();

        // S chunk = Q @ K_chunk^T  (4 k-tiles of 16, 8 n-tiles of 8)
        float sacc[8][4] = {};
#pragma unroll
        for (int kt = 0; kt < 4; kt++) {
#pragma unroll
            for (int nt = 0; nt < 8; nt++) {
                unsigned bfr[2];
                const __nv_bfloat16* kp = Ks + (nt * 8 + g) * AKB + kt * 16 + 2 * tig;
                bfr[0] = *(const unsigned*)kp;
                bfr[1] = *(const unsigned*)(kp + 8);
                mma_bf16(sacc[nt], qa[kt], bfr);
            }
        }

        // scale + bias + chunk max
        const float* bL = bias + ((long)b * NN + rowL) * NN + j0 + 2 * tig;
        const float* bH = bias + ((long)b * NN + rowH) * NN + j0 + 2 * tig;
        float cm0 = -1e30f, cm1 = -1e30f;
#pragma unroll
        for (int nt = 0; nt < 8; nt++) {
            float2 b0 = *(const float2*)(bL + nt * 8);
            float2 b1 = *(const float2*)(bH + nt * 8);
            sacc[nt][0] = sacc[nt][0] * 0.125f + b0.x;
            sacc[nt][1] = sacc[nt][1] * 0.125f + b0.y;
            sacc[nt][2] = sacc[nt][2] * 0.125f + b1.x;
            sacc[nt][3] = sacc[nt][3] * 0.125f + b1.y;
            cm0 = fmaxf(cm0, fmaxf(sacc[nt][0], sacc[nt][1]));
            cm1 = fmaxf(cm1, fmaxf(sacc[nt][2], sacc[nt][3]));
        }
        cm0 = fmaxf(cm0, __shfl_xor_sync(0xffffffffu, cm0, 1));
        cm0 = fmaxf(cm0, __shfl_xor_sync(0xffffffffu, cm0, 2));
        cm1 = fmaxf(cm1, __shfl_xor_sync(0xffffffffu, cm1, 1));
        cm1 = fmaxf(cm1, __shfl_xor_sync(0xffffffffu, cm1, 2));

        float mn0 = fmaxf(mr0, cm0), mn1 = fmaxf(mr1, cm1);
        float c0 = __expf(mr0 - mn0), c1 = __expf(mr1 - mn1);
        mr0 = mn0; mr1 = mn1;
        sum0 *= c0; sum1 *= c1;
#pragma unroll
        for (int nt = 0; nt < 8; nt++) {
            oacc[nt][0] *= c0; oacc[nt][1] *= c0;
            oacc[nt][2] *= c1; oacc[nt][3] *= c1;
        }

        // exp + register-direct P packs + O += P @ V (per kt-pair)
#pragma unroll
        for (int kt = 0; kt < 4; kt++) {
            unsigned pa[4];
#pragma unroll
            for (int s = 0; s < 2; s++) {       // nt = 2*kt + s
                int nt = 2 * kt + s;
                float p0 = __expf(sacc[nt][0] - mr0);
                float p1 = __expf(sacc[nt][1] - mr0);
                float p2 = __expf(sacc[nt][2] - mr1);
                float p3 = __expf(sacc[nt][3] - mr1);
                sum0 += p0 + p1;
                sum1 += p2 + p3;
                __nv_bfloat162 tL = __floats2bfloat162_rn(p0, p1);
                __nv_bfloat162 tH = __floats2bfloat162_rn(p2, p3);
                pa[2 * s]     = *(unsigned*)&tL;
                pa[2 * s + 1] = *(unsigned*)&tH;
            }
            int k2 = kt * 16 + 2 * tig;
#pragma unroll
            for (int nt = 0; nt < 8; nt++) {
                unsigned bfr[2];
                const __nv_bfloat16* vp = Vt + (nt * 8 + g) * AKB + k2;
                bfr[0] = *(const unsigned*)vp;
                bfr[1] = *(const unsigned*)(vp + 8);
                mma_bf16(oacc[nt], pa, bfr);
            }
        }
    }

    // Cross-lane reduction of row sums
    sum0 += __shfl_xor_sync(0xffffffffu, sum0, 1);
    sum0 += __shfl_xor_sync(0xffffffffu, sum0, 2);
    sum1 += __shfl_xor_sync(0xffffffffu, sum1, 1);
    sum1 += __shfl_xor_sync(0xffffffffu, sum1, 2);

    float inv0 = 1.f / sum0, inv1 = 1.f / sum1;
    float* oL = o + ((long)(b * NN + rowL)) * INNER + h * DH;
    float* oH = o + ((long)(b * NN + rowH)) * INNER + h * DH;
#pragma unroll
    for (int nt = 0; nt < 8; nt++) {
        int c = nt * 8 + 2 * tig;
        float2 w0, w1;
        w0.x = oacc[nt][0] * inv0; w0.y = oacc[nt][1] * inv0;
        w1.x = oacc[nt][2] * inv1; w1.y = oacc[nt][3] * inv1;
        *(float2*)&oL[c] = w0;
        *(float2*)&oH[c] = w1;
    }
}

// ---------------------------------------------------------------------------
// Head: mean-pool over N, LayerNorm, dot with Wf
// ---------------------------------------------------------------------------
__global__ void head_kernel(const float* __restrict__ x, const float* __restrict__ g,
                            const float* __restrict__ be, const float* __restrict__ Wf,
                            const float* __restrict__ bf, float* __restrict__ out)
{
    __shared__ float pool[DLAT];
    int b = blockIdx.x;
    int t = threadIdx.x;     // 128 threads
    if (t < DLAT) {
        float s = 0.f;
        const float* xb = x + (long)b * NN * DLAT + t;
        for (int n = 0; n < NN; n++) s += xb[n * DLAT];
        pool[t] = s * (1.f / NN);
    }
    __syncthreads();
    if (t < 32) {
        float v0 = pool[t], v1 = pool[t + 32];
        float v2 = (t + 64 < DLAT) ? pool[t + 64] : 0.f;
        float s = v0 + v1 + v2;
#pragma unroll
        for (int o = 16; o; o >>= 1) s += __shfl_xor_sync(0xffffffffu, s, o);
        float mean = s * (1.f / DLAT);
        float d0 = v0 - mean, d1 = v1 - mean;
        float d2 = (t + 64 < DLAT) ? (v2 - mean) : 0.f;
        float vs = d0 * d0 + d1 * d1 + d2 * d2;
#pragma unroll
        for (int o = 16; o; o >>= 1) vs += __shfl_xor_sync(0xffffffffu, vs, o);
        float inv = rsqrtf(vs * (1.f / DLAT) + 1e-5f);
        float dot = (d0 * inv * g[t] + be[t]) * Wf[t]
                  + (d1 * inv * g[t + 32] + be[t + 32]) * Wf[t + 32];
        if (t + 64 < DLAT)
            dot += (d2 * inv * g[t + 64] + be[t + 64]) * Wf[t + 64];
#pragma unroll
        for (int o = 16; o; o >>= 1) dot += __shfl_xor_sync(0xffffffffu, dot, o);
        if (t == 0) out[b] = dot + bf[0];
    }
}

// ---------------------------------------------------------------------------
// Launch
// ---------------------------------------------------------------------------
extern "C" void kernel_launch(void* const* d_in, const int* in_sizes, int n_in,
                              void* d_out, int out_size)
{
    const int*   spatial_pos = (const int*)d_in[0];
    const int*   edge_input  = (const int*)d_in[1];
    const int*   x_nodes     = (const int*)d_in[2];
    const int*   indeg       = (const int*)d_in[3];
    const int*   outdeg      = (const int*)d_in[4];
    const float* atom_emb    = (const float*)d_in[5];
    const float* indeg_emb   = (const float*)d_in[6];
    const float* outdeg_emb  = (const float*)d_in[7];
    const float* edge_emb    = (const float*)d_in[8];
    const float* edge_dis_w  = (const float*)d_in[9];
    const float* spatial_emb = (const float*)d_in[10];
    const float* ln1_g = (const float*)d_in[11];
    const float* ln1_b = (const float*)d_in[12];
    const float* Wq    = (const float*)d_in[13];
    const float* Wkv   = (const float*)d_in[14];
    const float* Wo    = (const float*)d_in[15];
    const float* bo    = (const float*)d_in[16];
    const float* ln2_g = (const float*)d_in[17];
    const float* ln2_b = (const float*)d_in[18];
    const float* W1    = (const float*)d_in[19];
    const float* b1    = (const float*)d_in[20];
    const float* W2    = (const float*)d_in[21];
    const float* b2    = (const float*)d_in[22];
    const float* lnf_g = (const float*)d_in[23];
    const float* lnf_b = (const float*)d_in[24];
    const float* Wf    = (const float*)d_in[25];
    const float* bf    = (const float*)d_in[26];
    float* out = (float*)d_out;

    float *gx, *go, *gf, *gb;
    __nv_bfloat16* gqkv;
    cudaGetSymbolAddress((void**)&gx,   g_x);
    cudaGetSymbolAddress((void**)&gqkv, g_qkv);
    cudaGetSymbolAddress((void**)&go,   g_o);
    cudaGetSymbolAddress((void**)&gf,   g_f);
    cudaGetSymbolAddress((void**)&gb,   g_bias);

    cudaFuncSetAttribute(attn_kernel,
                         cudaFuncAttributeMaxDynamicSharedMemorySize, ATTN_SMEM);
    cudaFuncSetAttribute(panel_gemm<0>,
                         cudaFuncAttributeMaxDynamicSharedMemorySize, PANEL_SMEM);
    cudaFuncSetAttribute(panel_gemm<2>,
                         cudaFuncAttributeMaxDynamicSharedMemorySize, PANEL_SMEM);

    bias_kernel<<<BB * NN, 128>>>(spatial_pos, edge_input, edge_emb,
                                  edge_dis_w, spatial_emb, gb);
    embed_kernel<<<ROWS, DLAT>>>(x_nodes, indeg, outdeg,
                                 atom_emb, indeg_emb, outdeg_emb, gx);

    for (int l = 0; l < DEPTH; l++) {
        panel_gemm<0><<<dim3(24, ROWS / 128), 256, PANEL_SMEM>>>(
            gx, ln1_g + l * DLAT, ln1_b + l * DLAT,
            Wq + (long)l * DLAT * INNER, Wkv + (long)l * DLAT * 2 * INNER,
            INNER, 2 * INNER, nullptr, (void*)gqkv, 3 * INNER);
        attn_kernel<<<BB * NH, 256, ATTN_SMEM>>>(gqkv, gb, go);
        mma_gemm<1><<<dim3(2, ROWS / GBM), 256>>>(
            go, Wo + (long)l * INNER * DLAT, bo + l * DLAT, gx,
            gx, ROWS, INNER, DLAT, DLAT, 0);
        panel_gemm<2><<<dim3(3, ROWS / 128), 256, PANEL_SMEM>>>(
            gx, ln2_g + l * DLAT, ln2_b + l * DLAT,
            W1 + (long)l * DLAT * FFD, nullptr,
            FFD, 0, b1 + l * FFD, (void*)gf, FFD);
        mma_gemm<1><<<dim3(2, ROWS / GBM), 256>>>(
            gf, W2 + (long)l * FFD * DLAT, b2 + l * DLAT, gx,
            gx, ROWS, FFD, DLAT, DLAT, 0);
    }

    head_kernel<<<BB, 128>>>(gx, lnf_g, lnf_b, Wf, bf, out);
}

// round 14
// speedup vs baseline: 1.0629x; 1.0035x over previous
#include <cuda_runtime.h>
#include <cuda_bf16.h>
#include <math.h>

// Problem constants
#define BB 64
#define NN 128
#define DLAT 80
#define NH 8
#define DH 64
#define INNER 512
#define FFD 160
#define MHD 20
#define DEPTH 24
#define ROWS (BB * NN)   // 8192

// ---------------------------------------------------------------------------
// Scratch (device globals; no allocation allowed)
// ---------------------------------------------------------------------------
__device__ float g_x[ROWS * DLAT];                  // residual stream
__device__ __nv_bfloat16 g_qkv[ROWS * 3 * INNER];   // fused Q|K|V (bf16, stride 1536)
__device__ float g_o[ROWS * INNER];                 // attention output
__device__ float g_f[ROWS * FFD];                   // FF hidden
__device__ float g_bias[BB * NN * NN];              // graph attention bias

// ---------------------------------------------------------------------------
// helpers
// ---------------------------------------------------------------------------
__device__ __forceinline__ float to_tf32(float x)
{
    float r;
    asm("cvt.rna.tf32.f32 %0, %1;" : "=f"(r) : "f"(x));
    return r;
}

__device__ __forceinline__ void mma_tf32(float* c, const float* a, const float* b)
{
    asm volatile(
        "mma.sync.aligned.m16n8k8.row.col.f32.tf32.tf32.f32 "
        "{%0,%1,%2,%3}, {%4,%5,%6,%7}, {%8,%9}, {%0,%1,%2,%3};"
        : "+f"(c[0]), "+f"(c[1]), "+f"(c[2]), "+f"(c[3])
        : "r"(__float_as_uint(a[0])), "r"(__float_as_uint(a[1])),
          "r"(__float_as_uint(a[2])), "r"(__float_as_uint(a[3])),
          "r"(__float_as_uint(b[0])), "r"(__float_as_uint(b[1])));
}

__device__ __forceinline__ void mma_bf16(float* c, const unsigned* a, const unsigned* b)
{
    asm volatile(
        "mma.sync.aligned.m16n8k16.row.col.f32.bf16.bf16.f32 "
        "{%0,%1,%2,%3}, {%4,%5,%6,%7}, {%8,%9}, {%0,%1,%2,%3};"
        : "+f"(c[0]), "+f"(c[1]), "+f"(c[2]), "+f"(c[3])
        : "r"(a[0]), "r"(a[1]), "r"(a[2]), "r"(a[3]),
          "r"(b[0]), "r"(b[1]));
}

// ---------------------------------------------------------------------------
// Graph bias
// ---------------------------------------------------------------------------
__global__ void bias_kernel(const int* __restrict__ spatial_pos,
                            const int* __restrict__ edge_input,
                            const float* __restrict__ edge_emb,
                            const float* __restrict__ edge_dis_w,
                            const float* __restrict__ spatial_emb,
                            float* __restrict__ bias)
{
    __shared__ float s_edge[64];
    __shared__ float s_w[MHD];
    __shared__ float s_sp[40];
    int t = threadIdx.x;               // 128 threads
    if (t < 64) s_edge[t] = edge_emb[t];
    if (t < MHD) s_w[t] = edge_dis_w[t];
    if (t >= 64 && t < 104) s_sp[t - 64] = spatial_emb[t - 64];
    __syncthreads();

    long bi = blockIdx.x;              // b*N + i
    int j = t;
    const int* ei = edge_input + (bi * NN + j) * (MHD * 3);
    float acc = 0.f;
#pragma unroll
    for (int hh = 0; hh < MHD; hh++) {
        float e = (s_edge[ei[hh * 3 + 0]] + s_edge[ei[hh * 3 + 1]] +
                   s_edge[ei[hh * 3 + 2]]) * (1.f / 3.f);
        acc += e * s_w[hh];
    }
    int sp0 = spatial_pos[bi * NN + j];
    int sp = (sp0 == 0) ? 1 : sp0;
    sp = (sp > 1) ? sp - 1 : sp;
    sp = min(sp, MHD);
    bias[bi * NN + j] = acc / (float)sp + s_sp[sp0];
}

// ---------------------------------------------------------------------------
// Node embedding
// ---------------------------------------------------------------------------
__global__ void embed_kernel(const int* __restrict__ x_nodes,
                             const int* __restrict__ indeg,
                             const int* __restrict__ outdeg,
                             const float* __restrict__ atom_emb,
                             const float* __restrict__ indeg_emb,
                             const float* __restrict__ outdeg_emb,
                             float* __restrict__ x)
{
    int r = blockIdx.x;      // 8192 rows
    int d = threadIdx.x;     // 80
    int a = x_nodes[r], i = indeg[r], o = outdeg[r];
    x[(long)r * DLAT + d] = atom_emb[a * DLAT + d] + indeg_emb[i * DLAT + d]
                          + outdeg_emb[o * DLAT + d];
}

// ---------------------------------------------------------------------------
// Panel GEMM with fused LayerNorm (K = DLAT = 80 only). 3 blocks/SM.
//   EPI 0: store bf16 (QKV path)   EPI 2: gelu_exact(acc + bias[n]), fp32
// ---------------------------------------------------------------------------
#define PAST 84
#define PANEL_SMEM ((128 + 64) * PAST * 4)   // 64512 bytes

template <int EPI>
__global__ void __launch_bounds__(256, 3) panel_gemm(
    const float* __restrict__ X,
    const float* __restrict__ lng, const float* __restrict__ lnb,
    const float* __restrict__ Wa, const float* __restrict__ Wb,
    int NcA, int NcB,
    const float* __restrict__ bias,
    void* __restrict__ Cout, int ldc)
{
    extern __shared__ float sm[];
    float* As = sm;                // [128][84]
    float* Bs = sm + 128 * PAST;   // [64][84]

    int bm = blockIdx.y * 128;
    int n_glob = blockIdx.x * 64;
    const float* W; int Wn; int wcol;
    if (n_glob < NcA) { W = Wa; Wn = NcA; wcol = n_glob; }
    else             { W = Wb; Wn = NcB; wcol = n_glob - NcA; }
    int NcTot = NcA + NcB;

    int t = threadIdx.x;

    {   // A panel: load 128x80, fused LayerNorm, tf32 store
        int r = t >> 1, half = t & 1;
        const float* ar = X + (long)(bm + r) * DLAT + half * 40;
        float* ad = As + r * PAST + half * 40;
        float s = 0.f;
#pragma unroll
        for (int i = 0; i < 40; i += 4) {
            float4 a4 = *(const float4*)(ar + i);
            *(float4*)(ad + i) = a4;
            s += (a4.x + a4.y) + (a4.z + a4.w);
        }
        s += __shfl_xor_sync(0xffffffffu, s, 1);
        float mean = s * (1.f / DLAT);
        float vs = 0.f;
#pragma unroll
        for (int i = 0; i < 40; i++) { float d = ad[i] - mean; vs += d * d; }
        vs += __shfl_xor_sync(0xffffffffu, vs, 1);
        float inv = rsqrtf(vs * (1.f / DLAT) + 1e-5f);
        const float* gg = lng + half * 40;
        const float* bb = lnb + half * 40;
#pragma unroll
        for (int i = 0; i < 40; i++)
            ad[i] = to_tf32((ad[i] - mean) * inv * gg[i] + bb[i]);
    }

    {   // B panel: transpose-stage W[k][wcol+n] -> Bs[n][k] (tf32)
        int kr = t >> 4;          // 0..15
        int n0 = (t & 15) * 4;    // 0..60
#pragma unroll
        for (int kb = 0; kb < DLAT; kb += 16) {
            int k = kb + kr;
            float4 w4 = make_float4(0.f, 0.f, 0.f, 0.f);
            if (wcol + n0 < Wn) {
                const float* wp = W + (long)k * Wn + wcol + n0;
                if (wcol + n0 + 3 < Wn) {
                    w4 = *(const float4*)wp;
                } else {
                    w4.x = wp[0];
                    if (wcol + n0 + 1 < Wn) w4.y = wp[1];
                    if (wcol + n0 + 2 < Wn) w4.z = wp[2];
                }
            }
            Bs[(n0 + 0) * PAST + k] = to_tf32(w4.x);
            Bs[(n0 + 1) * PAST + k] = to_tf32(w4.y);
            Bs[(n0 + 2) * PAST + k] = to_tf32(w4.z);
            Bs[(n0 + 3) * PAST + k] = to_tf32(w4.w);
        }
    }
    __syncthreads();

    int warp = t >> 5, lane = t & 31;
    int g = lane >> 2, tig = lane & 3;
    int warpM = warp >> 1, warpN = warp & 1;

    float acc[2][4][4] = {};

#pragma unroll
    for (int kt = 0; kt < 10; kt++) {
        int kk = kt * 8;
        float af[2][4];
#pragma unroll
        for (int mt = 0; mt < 2; mt++) {
            int r = warpM * 32 + mt * 16;
            af[mt][0] = As[(r + g) * PAST + kk + tig];
            af[mt][1] = As[(r + g + 8) * PAST + kk + tig];
            af[mt][2] = As[(r + g) * PAST + kk + tig + 4];
            af[mt][3] = As[(r + g + 8) * PAST + kk + tig + 4];
        }
#pragma unroll
        for (int nt = 0; nt < 4; nt++) {
            float bf[2];
            int n = warpN * 32 + nt * 8 + g;
            bf[0] = Bs[n * PAST + kk + tig];
            bf[1] = Bs[n * PAST + kk + tig + 4];
#pragma unroll
            for (int mt = 0; mt < 2; mt++)
                mma_tf32(acc[mt][nt], af[mt], bf);
        }
    }

#pragma unroll
    for (int mt = 0; mt < 2; mt++) {
        long rL = bm + warpM * 32 + mt * 16 + g;
        long rH = rL + 8;
#pragma unroll
        for (int nt = 0; nt < 4; nt++) {
            int n = n_glob + warpN * 32 + nt * 8 + 2 * tig;
            if (n >= NcTot) continue;
            float v0 = acc[mt][nt][0], v1 = acc[mt][nt][1];
            float v2 = acc[mt][nt][2], v3 = acc[mt][nt][3];
            if (EPI == 0) {
                __nv_bfloat16* Cb = (__nv_bfloat16*)Cout;
                *(__nv_bfloat162*)&Cb[rL * ldc + n] = __floats2bfloat162_rn(v0, v1);
                *(__nv_bfloat162*)&Cb[rH * ldc + n] = __floats2bfloat162_rn(v2, v3);
            } else {
                float b0 = bias[n], b1 = bias[n + 1];
                v0 += b0; v1 += b1; v2 += b0; v3 += b1;
                v0 = 0.5f * v0 * (1.f + erff(v0 * 0.70710678118654752f));
                v1 = 0.5f * v1 * (1.f + erff(v1 * 0.70710678118654752f));
                v2 = 0.5f * v2 * (1.f + erff(v2 * 0.70710678118654752f));
                v3 = 0.5f * v3 * (1.f + erff(v3 * 0.70710678118654752f));
                float* Cf = (float*)Cout;
                float2 w0, w1;
                w0.x = v0; w0.y = v1;
                w1.x = v2; w1.y = v3;
                *(float2*)&Cf[rL * ldc + n] = w0;
                *(float2*)&Cf[rH * ldc + n] = w1;
            }
        }
    }
}

// ---------------------------------------------------------------------------
// Chunked tf32 GEMM for Wo (K=512) and FF2 (K=160). BM=64.
// Warps whose 16-col slice is entirely n >= Nc skip their mma (zero work,
// identical results: their acc stays 0 and epilogue guards n >= Nc).
//   EPI 1: +bias[n]+res[m,n]
// ---------------------------------------------------------------------------
#define GBM 64
#define GBN 64
#define GBK 16
#define GAS 20
#define GBS 20

template <int EPI>
__global__ void __launch_bounds__(256) mma_gemm(
    const float* __restrict__ A, const float* __restrict__ W,
    const float* __restrict__ bias, const float* __restrict__ res,
    float* __restrict__ C, int M, int K, int Nc, int ldc, int coff)
{
    __shared__ float As[GBM * GAS];
    __shared__ float Bs[GBN * GBS];
    int bm = blockIdx.y * GBM;
    int bn = blockIdx.x * GBN;
    int tid = threadIdx.x;
    int warp = tid >> 5, lane = tid & 31;
    int g = lane >> 2, tig = lane & 3;
    int warpM = warp >> 2, warpN = warp & 3;
    bool active = (bn + warpN * 16) < Nc;   // any valid col in warp's slice?

    float acc[2][2][4] = {};

    for (int k0 = 0; k0 < K; k0 += GBK) {
        {
            int m = tid >> 2;
            int kq = (tid & 3) * 4;
            float4 a4 = *(const float4*)(A + (long)(bm + m) * K + k0 + kq);
            float* ad = As + m * GAS + kq;
            ad[0] = to_tf32(a4.x); ad[1] = to_tf32(a4.y);
            ad[2] = to_tf32(a4.z); ad[3] = to_tf32(a4.w);
        }
        {
            int kr = tid >> 4;
            int n0 = (tid & 15) * 4;
            const float* wp = W + (long)(k0 + kr) * Nc + bn + n0;
            float4 w4 = make_float4(0.f, 0.f, 0.f, 0.f);
            if (bn + n0 + 3 < Nc) {
                w4 = *(const float4*)wp;
            } else if (bn + n0 < Nc) {
                w4.x = wp[0];
                if (bn + n0 + 1 < Nc) w4.y = wp[1];
                if (bn + n0 + 2 < Nc) w4.z = wp[2];
            }
            Bs[(n0 + 0) * GBS + kr] = to_tf32(w4.x);
            Bs[(n0 + 1) * GBS + kr] = to_tf32(w4.y);
            Bs[(n0 + 2) * GBS + kr] = to_tf32(w4.z);
            Bs[(n0 + 3) * GBS + kr] = to_tf32(w4.w);
        }
        __syncthreads();
        if (active) {
#pragma unroll
            for (int kt = 0; kt < 2; kt++) {
                int kk = kt * 8;
                float af[2][4];
#pragma unroll
                for (int mt = 0; mt < 2; mt++) {
                    int r = warpM * 32 + mt * 16;
                    af[mt][0] = As[(r + g) * GAS + kk + tig];
                    af[mt][1] = As[(r + g + 8) * GAS + kk + tig];
                    af[mt][2] = As[(r + g) * GAS + kk + tig + 4];
                    af[mt][3] = As[(r + g + 8) * GAS + kk + tig + 4];
                }
#pragma unroll
                for (int nt = 0; nt < 2; nt++) {
                    float bf[2];
                    int n = warpN * 16 + nt * 8 + g;
                    bf[0] = Bs[n * GBS + kk + tig];
                    bf[1] = Bs[n * GBS + kk + tig + 4];
#pragma unroll
                    for (int mt = 0; mt < 2; mt++)
                        mma_tf32(acc[mt][nt], af[mt], bf);
                }
            }
        }
        __syncthreads();
    }

    if (!active) return;
#pragma unroll
    for (int mt = 0; mt < 2; mt++) {
        long rL = bm + warpM * 32 + mt * 16 + g;
        long rH = rL + 8;
#pragma unroll
        for (int nt = 0; nt < 2; nt++) {
            int n = bn + warpN * 16 + nt * 8 + 2 * tig;
            if (n >= Nc) continue;
            float v0 = acc[mt][nt][0], v1 = acc[mt][nt][1];
            float v2 = acc[mt][nt][2], v3 = acc[mt][nt][3];
            if (EPI == 1) {
                float b0 = bias[n], b1 = bias[n + 1];
                const float* rL_p = res + rL * Nc + n;
                const float* rH_p = res + rH * Nc + n;
                v0 += b0 + rL_p[0]; v1 += b1 + rL_p[1];
                v2 += b0 + rH_p[0]; v3 += b1 + rH_p[1];
            }
            float2 w0, w1;
            w0.x = v0; w0.y = v1;
            w1.x = v2; w1.y = v3;
            *(float2*)&C[rL * ldc + coff + n] = w0;
            *(float2*)&C[rH * ldc + coff + n] = w1;
        }
    }
}

// ---------------------------------------------------------------------------
// bf16 flash attention, register-direct P; qkv bf16 in global.
// Smem: Ks[64][72] + Vt[64][72] + Qs[128][72] (bf16) = 36864 B -> 2 blocks/SM.
// ---------------------------------------------------------------------------
#define AKB 72
#define ATTN_SMEM ((64 + 64 + 128) * AKB * 2)   // 36864 bytes

__global__ void __launch_bounds__(256, 2) attn_kernel(
    const __nv_bfloat16* __restrict__ qkv, const float* __restrict__ bias,
    float* __restrict__ o)
{
    extern __shared__ float sm[];
    __nv_bfloat16* Ks = (__nv_bfloat16*)sm;        // [64][72]  K chunk (rows j)
    __nv_bfloat16* Vt = Ks + 64 * AKB;             // [64][72]  V chunk (rows d, cols j)
    __nv_bfloat16* Qs = Vt + 64 * AKB;             // [128][72] Q staging

    int bh = blockIdx.x;
    int b = bh >> 3, h = bh & 7;
    int t = threadIdx.x;

    // Stage Q (already bf16)
    {
        int r = t >> 1, half = t & 1;
        const __nv_bfloat16* qr = qkv + ((long)(b * NN + r)) * 1536 + h * DH + half * 32;
        __nv_bfloat16* qd = Qs + r * AKB + half * 32;
#pragma unroll
        for (int i = 0; i < 32; i += 8)
            *(uint4*)(qd + i) = *(const uint4*)(qr + i);
    }
    __syncthreads();

    int warp = t >> 5, lane = t & 31;
    int g = lane >> 2, tig = lane & 3;
    int m0 = warp * 16;
    int rowL = m0 + g, rowH = m0 + g + 8;

    unsigned qa[4][4];
#pragma unroll
    for (int kt = 0; kt < 4; kt++) {
        int k2 = kt * 16 + 2 * tig;
        qa[kt][0] = *(const unsigned*)(Qs + rowL * AKB + k2);
        qa[kt][1] = *(const unsigned*)(Qs + rowH * AKB + k2);
        qa[kt][2] = *(const unsigned*)(Qs + rowL * AKB + k2 + 8);
        qa[kt][3] = *(const unsigned*)(Qs + rowH * AKB + k2 + 8);
    }

    float mr0 = -1e30f, mr1 = -1e30f, sum0 = 0.f, sum1 = 0.f;
    float oacc[8][4] = {};

#pragma unroll
    for (int jc = 0; jc < 2; jc++) {
        int j0 = jc * 64;
        __syncthreads();   // K/V chunk reuse fence
        {
            int r2 = t >> 2;              // local j 0..63
            int q4o = (t & 3) * 16;       // d base
            const __nv_bfloat16* kr = qkv + ((long)(b * NN + j0 + r2)) * 1536 + 512
                                      + h * DH + q4o;
            const __nv_bfloat16* vr = kr + 512;
            __nv_bfloat16* kd = Ks + r2 * AKB + q4o;
            *(uint4*)(kd)     = *(const uint4*)(kr);
            *(uint4*)(kd + 8) = *(const uint4*)(kr + 8);
            __nv_bfloat16 vbuf[16];
            *(uint4*)(vbuf)     = *(const uint4*)(vr);
            *(uint4*)(vbuf + 8) = *(const uint4*)(vr + 8);
#pragma unroll
            for (int i = 0; i < 16; i++)
                Vt[(q4o + i) * AKB + r2] = vbuf[i];
        }
        __syncthreads();

        // S chunk = Q @ K_chunk^T
        float sacc[8][4] = {};
#pragma unroll
        for (int kt = 0; kt < 4; kt++) {
#pragma unroll
            for (int nt = 0; nt < 8; nt++) {
                unsigned bfr[2];
                const __nv_bfloat16* kp = Ks + (nt * 8 + g) * AKB + kt * 16 + 2 * tig;
                bfr[0] = *(const unsigned*)kp;
                bfr[1] = *(const unsigned*)(kp + 8);
                mma_bf16(sacc[nt], qa[kt], bfr);
            }
        }

        // scale + bias + chunk max
        const float* bL = bias + ((long)b * NN + rowL) * NN + j0 + 2 * tig;
        const float* bH = bias + ((long)b * NN + rowH) * NN + j0 + 2 * tig;
        float cm0 = -1e30f, cm1 = -1e30f;
#pragma unroll
        for (int nt = 0; nt < 8; nt++) {
            float2 b0 = *(const float2*)(bL + nt * 8);
            float2 b1 = *(const float2*)(bH + nt * 8);
            sacc[nt][0] = sacc[nt][0] * 0.125f + b0.x;
            sacc[nt][1] = sacc[nt][1] * 0.125f + b0.y;
            sacc[nt][2] = sacc[nt][2] * 0.125f + b1.x;
            sacc[nt][3] = sacc[nt][3] * 0.125f + b1.y;
            cm0 = fmaxf(cm0, fmaxf(sacc[nt][0], sacc[nt][1]));
            cm1 = fmaxf(cm1, fmaxf(sacc[nt][2], sacc[nt][3]));
        }
        cm0 = fmaxf(cm0, __shfl_xor_sync(0xffffffffu, cm0, 1));
        cm0 = fmaxf(cm0, __shfl_xor_sync(0xffffffffu, cm0, 2));
        cm1 = fmaxf(cm1, __shfl_xor_sync(0xffffffffu, cm1, 1));
        cm1 = fmaxf(cm1, __shfl_xor_sync(0xffffffffu, cm1, 2));

        float mn0 = fmaxf(mr0, cm0), mn1 = fmaxf(mr1, cm1);
        float c0 = __expf(mr0 - mn0), c1 = __expf(mr1 - mn1);
        mr0 = mn0; mr1 = mn1;
        sum0 *= c0; sum1 *= c1;
#pragma unroll
        for (int nt = 0; nt < 8; nt++) {
            oacc[nt][0] *= c0; oacc[nt][1] *= c0;
            oacc[nt][2] *= c1; oacc[nt][3] *= c1;
        }

        // exp + register-direct P packs + O += P @ V (per kt-pair)
#pragma unroll
        for (int kt = 0; kt < 4; kt++) {
            unsigned pa[4];
#pragma unroll
            for (int s = 0; s < 2; s++) {       // nt = 2*kt + s
                int nt = 2 * kt + s;
                float p0 = __expf(sacc[nt][0] - mr0);
                float p1 = __expf(sacc[nt][1] - mr0);
                float p2 = __expf(sacc[nt][2] - mr1);
                float p3 = __expf(sacc[nt][3] - mr1);
                sum0 += p0 + p1;
                sum1 += p2 + p3;
                __nv_bfloat162 tL = __floats2bfloat162_rn(p0, p1);
                __nv_bfloat162 tH = __floats2bfloat162_rn(p2, p3);
                pa[2 * s]     = *(unsigned*)&tL;
                pa[2 * s + 1] = *(unsigned*)&tH;
            }
            int k2 = kt * 16 + 2 * tig;
#pragma unroll
            for (int nt = 0; nt < 8; nt++) {
                unsigned bfr[2];
                const __nv_bfloat16* vp = Vt + (nt * 8 + g) * AKB + k2;
                bfr[0] = *(const unsigned*)vp;
                bfr[1] = *(const unsigned*)(vp + 8);
                mma_bf16(oacc[nt], pa, bfr);
            }
        }
    }

    sum0 += __shfl_xor_sync(0xffffffffu, sum0, 1);
    sum0 += __shfl_xor_sync(0xffffffffu, sum0, 2);
    sum1 += __shfl_xor_sync(0xffffffffu, sum1, 1);
    sum1 += __shfl_xor_sync(0xffffffffu, sum1, 2);

    float inv0 = 1.f / sum0, inv1 = 1.f / sum1;
    float* oL = o + ((long)(b * NN + rowL)) * INNER + h * DH;
    float* oH = o + ((long)(b * NN + rowH)) * INNER + h * DH;
#pragma unroll
    for (int nt = 0; nt < 8; nt++) {
        int c = nt * 8 + 2 * tig;
        float2 w0, w1;
        w0.x = oacc[nt][0] * inv0; w0.y = oacc[nt][1] * inv0;
        w1.x = oacc[nt][2] * inv1; w1.y = oacc[nt][3] * inv1;
        *(float2*)&oL[c] = w0;
        *(float2*)&oH[c] = w1;
    }
}

// ---------------------------------------------------------------------------
// Head: mean-pool over N, LayerNorm, dot with Wf
// ---------------------------------------------------------------------------
__global__ void head_kernel(const float* __restrict__ x, const float* __restrict__ g,
                            const float* __restrict__ be, const float* __restrict__ Wf,
                            const float* __restrict__ bf, float* __restrict__ out)
{
    __shared__ float pool[DLAT];
    int b = blockIdx.x;
    int t = threadIdx.x;     // 128 threads
    if (t < DLAT) {
        float s = 0.f;
        const float* xb = x + (long)b * NN * DLAT + t;
        for (int n = 0; n < NN; n++) s += xb[n * DLAT];
        pool[t] = s * (1.f / NN);
    }
    __syncthreads();
    if (t < 32) {
        float v0 = pool[t], v1 = pool[t + 32];
        float v2 = (t + 64 < DLAT) ? pool[t + 64] : 0.f;
        float s = v0 + v1 + v2;
#pragma unroll
        for (int o = 16; o; o >>= 1) s += __shfl_xor_sync(0xffffffffu, s, o);
        float mean = s * (1.f / DLAT);
        float d0 = v0 - mean, d1 = v1 - mean;
        float d2 = (t + 64 < DLAT) ? (v2 - mean) : 0.f;
        float vs = d0 * d0 + d1 * d1 + d2 * d2;
#pragma unroll
        for (int o = 16; o; o >>= 1) vs += __shfl_xor_sync(0xffffffffu, vs, o);
        float inv = rsqrtf(vs * (1.f / DLAT) + 1e-5f);
        float dot = (d0 * inv * g[t] + be[t]) * Wf[t]
                  + (d1 * inv * g[t + 32] + be[t + 32]) * Wf[t + 32];
        if (t + 64 < DLAT)
            dot += (d2 * inv * g[t + 64] + be[t + 64]) * Wf[t + 64];
#pragma unroll
        for (int o = 16; o; o >>= 1) dot += __shfl_xor_sync(0xffffffffu, dot, o);
        if (t == 0) out[b] = dot + bf[0];
    }
}

// ---------------------------------------------------------------------------
// Launch
// ---------------------------------------------------------------------------
extern "C" void kernel_launch(void* const* d_in, const int* in_sizes, int n_in,
                              void* d_out, int out_size)
{
    const int*   spatial_pos = (const int*)d_in[0];
    const int*   edge_input  = (const int*)d_in[1];
    const int*   x_nodes     = (const int*)d_in[2];
    const int*   indeg       = (const int*)d_in[3];
    const int*   outdeg      = (const int*)d_in[4];
    const float* atom_emb    = (const float*)d_in[5];
    const float* indeg_emb   = (const float*)d_in[6];
    const float* outdeg_emb  = (const float*)d_in[7];
    const float* edge_emb    = (const float*)d_in[8];
    const float* edge_dis_w  = (const float*)d_in[9];
    const float* spatial_emb = (const float*)d_in[10];
    const float* ln1_g = (const float*)d_in[11];
    const float* ln1_b = (const float*)d_in[12];
    const float* Wq    = (const float*)d_in[13];
    const float* Wkv   = (const float*)d_in[14];
    const float* Wo    = (const float*)d_in[15];
    const float* bo    = (const float*)d_in[16];
    const float* ln2_g = (const float*)d_in[17];
    const float* ln2_b = (const float*)d_in[18];
    const float* W1    = (const float*)d_in[19];
    const float* b1    = (const float*)d_in[20];
    const float* W2    = (const float*)d_in[21];
    const float* b2    = (const float*)d_in[22];
    const float* lnf_g = (const float*)d_in[23];
    const float* lnf_b = (const float*)d_in[24];
    const float* Wf    = (const float*)d_in[25];
    const float* bf    = (const float*)d_in[26];
    float* out = (float*)d_out;

    float *gx, *go, *gf, *gb;
    __nv_bfloat16* gqkv;
    cudaGetSymbolAddress((void**)&gx,   g_x);
    cudaGetSymbolAddress((void**)&gqkv, g_qkv);
    cudaGetSymbolAddress((void**)&go,   g_o);
    cudaGetSymbolAddress((void**)&gf,   g_f);
    cudaGetSymbolAddress((void**)&gb,   g_bias);

    cudaFuncSetAttribute(attn_kernel,
                         cudaFuncAttributeMaxDynamicSharedMemorySize, ATTN_SMEM);
    cudaFuncSetAttribute(panel_gemm<0>,
                         cudaFuncAttributeMaxDynamicSharedMemorySize, PANEL_SMEM);
    cudaFuncSetAttribute(panel_gemm<2>,
                         cudaFuncAttributeMaxDynamicSharedMemorySize, PANEL_SMEM);

    bias_kernel<<<BB * NN, 128>>>(spatial_pos, edge_input, edge_emb,
                                  edge_dis_w, spatial_emb, gb);
    embed_kernel<<<ROWS, DLAT>>>(x_nodes, indeg, outdeg,
                                 atom_emb, indeg_emb, outdeg_emb, gx);

    for (int l = 0; l < DEPTH; l++) {
        panel_gemm<0><<<dim3(24, ROWS / 128), 256, PANEL_SMEM>>>(
            gx, ln1_g + l * DLAT, ln1_b + l * DLAT,
            Wq + (long)l * DLAT * INNER, Wkv + (long)l * DLAT * 2 * INNER,
            INNER, 2 * INNER, nullptr, (void*)gqkv, 3 * INNER);
        attn_kernel<<<BB * NH, 256, ATTN_SMEM>>>(gqkv, gb, go);
        mma_gemm<1><<<dim3(2, ROWS / GBM), 256>>>(
            go, Wo + (long)l * INNER * DLAT, bo + l * DLAT, gx,
            gx, ROWS, INNER, DLAT, DLAT, 0);
        panel_gemm<2><<<dim3(3, ROWS / 128), 256, PANEL_SMEM>>>(
            gx, ln2_g + l * DLAT, ln2_b + l * DLAT,
            W1 + (long)l * DLAT * FFD, nullptr,
            FFD, 0, b1 + l * FFD, (void*)gf, FFD);
        mma_gemm<1><<<dim3(2, ROWS / GBM), 256>>>(
            gf, W2 + (long)l * FFD * DLAT, b2 + l * DLAT, gx,
            gx, ROWS, FFD, DLAT, DLAT, 0);
    }

    head_kernel<<<BB, 128>>>(gx, lnf_g, lnf_b, Wf, bf, out);
}

// round 15
// speedup vs baseline: 1.0641x; 1.0011x over previous
#include <cuda_runtime.h>
#include <cuda_bf16.h>
#include <math.h>

// Problem constants
#define BB 64
#define NN 128
#define DLAT 80
#define NH 8
#define DH 64
#define INNER 512
#define FFD 160
#define MHD 20
#define DEPTH 24
#define ROWS (BB * NN)   // 8192

// ---------------------------------------------------------------------------
// Scratch (device globals; no allocation allowed)
// ---------------------------------------------------------------------------
__device__ float g_x[ROWS * DLAT];                  // residual stream
__device__ __nv_bfloat16 g_qkv[ROWS * 3 * INNER];   // fused Q|K|V (bf16, stride 1536)
__device__ float g_o[ROWS * INNER];                 // attention output
__device__ float g_f[ROWS * FFD];                   // FF hidden
__device__ float g_bias[BB * NN * NN];              // graph attention bias

// ---------------------------------------------------------------------------
// helpers
// ---------------------------------------------------------------------------
__device__ __forceinline__ float to_tf32(float x)
{
    float r;
    asm("cvt.rna.tf32.f32 %0, %1;" : "=f"(r) : "f"(x));
    return r;
}

__device__ __forceinline__ void mma_tf32(float* c, const float* a, const float* b)
{
    asm volatile(
        "mma.sync.aligned.m16n8k8.row.col.f32.tf32.tf32.f32 "
        "{%0,%1,%2,%3}, {%4,%5,%6,%7}, {%8,%9}, {%0,%1,%2,%3};"
        : "+f"(c[0]), "+f"(c[1]), "+f"(c[2]), "+f"(c[3])
        : "r"(__float_as_uint(a[0])), "r"(__float_as_uint(a[1])),
          "r"(__float_as_uint(a[2])), "r"(__float_as_uint(a[3])),
          "r"(__float_as_uint(b[0])), "r"(__float_as_uint(b[1])));
}

__device__ __forceinline__ void mma_bf16(float* c, const unsigned* a, const unsigned* b)
{
    asm volatile(
        "mma.sync.aligned.m16n8k16.row.col.f32.bf16.bf16.f32 "
        "{%0,%1,%2,%3}, {%4,%5,%6,%7}, {%8,%9}, {%0,%1,%2,%3};"
        : "+f"(c[0]), "+f"(c[1]), "+f"(c[2]), "+f"(c[3])
        : "r"(a[0]), "r"(a[1]), "r"(a[2]), "r"(a[3]),
          "r"(b[0]), "r"(b[1]));
}

// ---------------------------------------------------------------------------
// Graph bias
// ---------------------------------------------------------------------------
__global__ void bias_kernel(const int* __restrict__ spatial_pos,
                            const int* __restrict__ edge_input,
                            const float* __restrict__ edge_emb,
                            const float* __restrict__ edge_dis_w,
                            const float* __restrict__ spatial_emb,
                            float* __restrict__ bias)
{
    __shared__ float s_edge[64];
    __shared__ float s_w[MHD];
    __shared__ float s_sp[40];
    int t = threadIdx.x;               // 128 threads
    if (t < 64) s_edge[t] = edge_emb[t];
    if (t < MHD) s_w[t] = edge_dis_w[t];
    if (t >= 64 && t < 104) s_sp[t - 64] = spatial_emb[t - 64];
    __syncthreads();

    long bi = blockIdx.x;              // b*N + i
    int j = t;
    const int* ei = edge_input + (bi * NN + j) * (MHD * 3);
    float acc = 0.f;
#pragma unroll
    for (int hh = 0; hh < MHD; hh++) {
        float e = (s_edge[ei[hh * 3 + 0]] + s_edge[ei[hh * 3 + 1]] +
                   s_edge[ei[hh * 3 + 2]]) * (1.f / 3.f);
        acc += e * s_w[hh];
    }
    int sp0 = spatial_pos[bi * NN + j];
    int sp = (sp0 == 0) ? 1 : sp0;
    sp = (sp > 1) ? sp - 1 : sp;
    sp = min(sp, MHD);
    bias[bi * NN + j] = acc / (float)sp + s_sp[sp0];
}

// ---------------------------------------------------------------------------
// Node embedding
// ---------------------------------------------------------------------------
__global__ void embed_kernel(const int* __restrict__ x_nodes,
                             const int* __restrict__ indeg,
                             const int* __restrict__ outdeg,
                             const float* __restrict__ atom_emb,
                             const float* __restrict__ indeg_emb,
                             const float* __restrict__ outdeg_emb,
                             float* __restrict__ x)
{
    int r = blockIdx.x;      // 8192 rows
    int d = threadIdx.x;     // 80
    int a = x_nodes[r], i = indeg[r], o = outdeg[r];
    x[(long)r * DLAT + d] = atom_emb[a * DLAT + d] + indeg_emb[i * DLAT + d]
                          + outdeg_emb[o * DLAT + d];
}

// ---------------------------------------------------------------------------
// Panel GEMM with fused LayerNorm (K = DLAT = 80 only). 3 blocks/SM.
//   EPI 0: store bf16 (QKV path)   EPI 2: gelu_exact(acc + bias[n]), fp32
// ---------------------------------------------------------------------------
#define PAST 84
#define PANEL_SMEM ((128 + 64) * PAST * 4)   // 64512 bytes

template <int EPI>
__global__ void __launch_bounds__(256, 3) panel_gemm(
    const float* __restrict__ X,
    const float* __restrict__ lng, const float* __restrict__ lnb,
    const float* __restrict__ Wa, const float* __restrict__ Wb,
    int NcA, int NcB,
    const float* __restrict__ bias,
    void* __restrict__ Cout, int ldc)
{
    extern __shared__ float sm[];
    float* As = sm;                // [128][84]
    float* Bs = sm + 128 * PAST;   // [64][84]

    int bm = blockIdx.y * 128;
    int n_glob = blockIdx.x * 64;
    const float* W; int Wn; int wcol;
    if (n_glob < NcA) { W = Wa; Wn = NcA; wcol = n_glob; }
    else             { W = Wb; Wn = NcB; wcol = n_glob - NcA; }
    int NcTot = NcA + NcB;

    int t = threadIdx.x;

    {   // A panel: load 128x80, fused LayerNorm, tf32 store
        int r = t >> 1, half = t & 1;
        const float* ar = X + (long)(bm + r) * DLAT + half * 40;
        float* ad = As + r * PAST + half * 40;
        float s = 0.f;
#pragma unroll
        for (int i = 0; i < 40; i += 4) {
            float4 a4 = *(const float4*)(ar + i);
            *(float4*)(ad + i) = a4;
            s += (a4.x + a4.y) + (a4.z + a4.w);
        }
        s += __shfl_xor_sync(0xffffffffu, s, 1);
        float mean = s * (1.f / DLAT);
        float vs = 0.f;
#pragma unroll
        for (int i = 0; i < 40; i++) { float d = ad[i] - mean; vs += d * d; }
        vs += __shfl_xor_sync(0xffffffffu, vs, 1);
        float inv = rsqrtf(vs * (1.f / DLAT) + 1e-5f);
        const float* gg = lng + half * 40;
        const float* bb = lnb + half * 40;
#pragma unroll
        for (int i = 0; i < 40; i++)
            ad[i] = to_tf32((ad[i] - mean) * inv * gg[i] + bb[i]);
    }

    {   // B panel: transpose-stage W[k][wcol+n] -> Bs[n][k] (tf32)
        int kr = t >> 4;          // 0..15
        int n0 = (t & 15) * 4;    // 0..60
#pragma unroll
        for (int kb = 0; kb < DLAT; kb += 16) {
            int k = kb + kr;
            float4 w4 = make_float4(0.f, 0.f, 0.f, 0.f);
            if (wcol + n0 < Wn) {
                const float* wp = W + (long)k * Wn + wcol + n0;
                if (wcol + n0 + 3 < Wn) {
                    w4 = *(const float4*)wp;
                } else {
                    w4.x = wp[0];
                    if (wcol + n0 + 1 < Wn) w4.y = wp[1];
                    if (wcol + n0 + 2 < Wn) w4.z = wp[2];
                }
            }
            Bs[(n0 + 0) * PAST + k] = to_tf32(w4.x);
            Bs[(n0 + 1) * PAST + k] = to_tf32(w4.y);
            Bs[(n0 + 2) * PAST + k] = to_tf32(w4.z);
            Bs[(n0 + 3) * PAST + k] = to_tf32(w4.w);
        }
    }
    __syncthreads();

    int warp = t >> 5, lane = t & 31;
    int g = lane >> 2, tig = lane & 3;
    int warpM = warp >> 1, warpN = warp & 1;

    float acc[2][4][4] = {};

#pragma unroll
    for (int kt = 0; kt < 10; kt++) {
        int kk = kt * 8;
        float af[2][4];
#pragma unroll
        for (int mt = 0; mt < 2; mt++) {
            int r = warpM * 32 + mt * 16;
            af[mt][0] = As[(r + g) * PAST + kk + tig];
            af[mt][1] = As[(r + g + 8) * PAST + kk + tig];
            af[mt][2] = As[(r + g) * PAST + kk + tig + 4];
            af[mt][3] = As[(r + g + 8) * PAST + kk + tig + 4];
        }
#pragma unroll
        for (int nt = 0; nt < 4; nt++) {
            float bf[2];
            int n = warpN * 32 + nt * 8 + g;
            bf[0] = Bs[n * PAST + kk + tig];
            bf[1] = Bs[n * PAST + kk + tig + 4];
#pragma unroll
            for (int mt = 0; mt < 2; mt++)
                mma_tf32(acc[mt][nt], af[mt], bf);
        }
    }

#pragma unroll
    for (int mt = 0; mt < 2; mt++) {
        long rL = bm + warpM * 32 + mt * 16 + g;
        long rH = rL + 8;
#pragma unroll
        for (int nt = 0; nt < 4; nt++) {
            int n = n_glob + warpN * 32 + nt * 8 + 2 * tig;
            if (n >= NcTot) continue;
            float v0 = acc[mt][nt][0], v1 = acc[mt][nt][1];
            float v2 = acc[mt][nt][2], v3 = acc[mt][nt][3];
            if (EPI == 0) {
                __nv_bfloat16* Cb = (__nv_bfloat16*)Cout;
                *(__nv_bfloat162*)&Cb[rL * ldc + n] = __floats2bfloat162_rn(v0, v1);
                *(__nv_bfloat162*)&Cb[rH * ldc + n] = __floats2bfloat162_rn(v2, v3);
            } else {
                float b0 = bias[n], b1 = bias[n + 1];
                v0 += b0; v1 += b1; v2 += b0; v3 += b1;
                v0 = 0.5f * v0 * (1.f + erff(v0 * 0.70710678118654752f));
                v1 = 0.5f * v1 * (1.f + erff(v1 * 0.70710678118654752f));
                v2 = 0.5f * v2 * (1.f + erff(v2 * 0.70710678118654752f));
                v3 = 0.5f * v3 * (1.f + erff(v3 * 0.70710678118654752f));
                float* Cf = (float*)Cout;
                float2 w0, w1;
                w0.x = v0; w0.y = v1;
                w1.x = v2; w1.y = v3;
                *(float2*)&Cf[rL * ldc + n] = w0;
                *(float2*)&Cf[rH * ldc + n] = w1;
            }
        }
    }
}

// ---------------------------------------------------------------------------
// Chunked tf32 GEMM for Wo (K=512) and FF2 (K=160). BM=64.
// Warps whose 16-col slice is entirely n >= Nc skip their mma (zero work,
// identical results: their acc stays 0 and epilogue guards n >= Nc).
//   EPI 1: +bias[n]+res[m,n]
// ---------------------------------------------------------------------------
#define GBM 64
#define GBN 64
#define GBK 16
#define GAS 20
#define GBS 20

template <int EPI>
__global__ void __launch_bounds__(256) mma_gemm(
    const float* __restrict__ A, const float* __restrict__ W,
    const float* __restrict__ bias, const float* __restrict__ res,
    float* __restrict__ C, int M, int K, int Nc, int ldc, int coff)
{
    __shared__ float As[GBM * GAS];
    __shared__ float Bs[GBN * GBS];
    int bm = blockIdx.y * GBM;
    int bn = blockIdx.x * GBN;
    int tid = threadIdx.x;
    int warp = tid >> 5, lane = tid & 31;
    int g = lane >> 2, tig = lane & 3;
    int warpM = warp >> 2, warpN = warp & 3;
    bool active = (bn + warpN * 16) < Nc;   // any valid col in warp's slice?

    float acc[2][2][4] = {};

    for (int k0 = 0; k0 < K; k0 += GBK) {
        {
            int m = tid >> 2;
            int kq = (tid & 3) * 4;
            float4 a4 = *(const float4*)(A + (long)(bm + m) * K + k0 + kq);
            float* ad = As + m * GAS + kq;
            ad[0] = to_tf32(a4.x); ad[1] = to_tf32(a4.y);
            ad[2] = to_tf32(a4.z); ad[3] = to_tf32(a4.w);
        }
        {
            int kr = tid >> 4;
            int n0 = (tid & 15) * 4;
            const float* wp = W + (long)(k0 + kr) * Nc + bn + n0;
            float4 w4 = make_float4(0.f, 0.f, 0.f, 0.f);
            if (bn + n0 + 3 < Nc) {
                w4 = *(const float4*)wp;
            } else if (bn + n0 < Nc) {
                w4.x = wp[0];
                if (bn + n0 + 1 < Nc) w4.y = wp[1];
                if (bn + n0 + 2 < Nc) w4.z = wp[2];
            }
            Bs[(n0 + 0) * GBS + kr] = to_tf32(w4.x);
            Bs[(n0 + 1) * GBS + kr] = to_tf32(w4.y);
            Bs[(n0 + 2) * GBS + kr] = to_tf32(w4.z);
            Bs[(n0 + 3) * GBS + kr] = to_tf32(w4.w);
        }
        __syncthreads();
        if (active) {
#pragma unroll
            for (int kt = 0; kt < 2; kt++) {
                int kk = kt * 8;
                float af[2][4];
#pragma unroll
                for (int mt = 0; mt < 2; mt++) {
                    int r = warpM * 32 + mt * 16;
                    af[mt][0] = As[(r + g) * GAS + kk + tig];
                    af[mt][1] = As[(r + g + 8) * GAS + kk + tig];
                    af[mt][2] = As[(r + g) * GAS + kk + tig + 4];
                    af[mt][3] = As[(r + g + 8) * GAS + kk + tig + 4];
                }
#pragma unroll
                for (int nt = 0; nt < 2; nt++) {
                    float bf[2];
                    int n = warpN * 16 + nt * 8 + g;
                    bf[0] = Bs[n * GBS + kk + tig];
                    bf[1] = Bs[n * GBS + kk + tig + 4];
#pragma unroll
                    for (int mt = 0; mt < 2; mt++)
                        mma_tf32(acc[mt][nt], af[mt], bf);
                }
            }
        }
        __syncthreads();
    }

    if (!active) return;
#pragma unroll
    for (int mt = 0; mt < 2; mt++) {
        long rL = bm + warpM * 32 + mt * 16 + g;
        long rH = rL + 8;
#pragma unroll
        for (int nt = 0; nt < 2; nt++) {
            int n = bn + warpN * 16 + nt * 8 + 2 * tig;
            if (n >= Nc) continue;
            float v0 = acc[mt][nt][0], v1 = acc[mt][nt][1];
            float v2 = acc[mt][nt][2], v3 = acc[mt][nt][3];
            if (EPI == 1) {
                float b0 = bias[n], b1 = bias[n + 1];
                const float* rL_p = res + rL * Nc + n;
                const float* rH_p = res + rH * Nc + n;
                v0 += b0 + rL_p[0]; v1 += b1 + rL_p[1];
                v2 += b0 + rH_p[0]; v3 += b1 + rH_p[1];
            }
            float2 w0, w1;
            w0.x = v0; w0.y = v1;
            w1.x = v2; w1.y = v3;
            *(float2*)&C[rL * ldc + coff + n] = w0;
            *(float2*)&C[rH * ldc + coff + n] = w1;
        }
    }
}

// ---------------------------------------------------------------------------
// bf16 flash attention, register-direct P; qkv bf16 in global.
// Smem: Ks[64][72] + Vt[64][72] + Qs[128][72] (bf16) = 36864 B -> 2 blocks/SM.
// ---------------------------------------------------------------------------
#define AKB 72
#define ATTN_SMEM ((64 + 64 + 128) * AKB * 2)   // 36864 bytes

__global__ void __launch_bounds__(256, 2) attn_kernel(
    const __nv_bfloat16* __restrict__ qkv, const float* __restrict__ bias,
    float* __restrict__ o)
{
    extern __shared__ float sm[];
    __nv_bfloat16* Ks = (__nv_bfloat16*)sm;        // [64][72]  K chunk (rows j)
    __nv_bfloat16* Vt = Ks + 64 * AKB;             // [64][72]  V chunk (rows d, cols j)
    __nv_bfloat16* Qs = Vt + 64 * AKB;             // [128][72] Q staging

    int bh = blockIdx.x;
    int b = bh >> 3, h = bh & 7;
    int t = threadIdx.x;

    // Stage Q (already bf16)
    {
        int r = t >> 1, half = t & 1;
        const __nv_bfloat16* qr = qkv + ((long)(b * NN + r)) * 1536 + h * DH + half * 32;
        __nv_bfloat16* qd = Qs + r * AKB + half * 32;
#pragma unroll
        for (int i = 0; i < 32; i += 8)
            *(uint4*)(qd + i) = *(const uint4*)(qr + i);
    }
    __syncthreads();

    int warp = t >> 5, lane = t & 31;
    int g = lane >> 2, tig = lane & 3;
    int m0 = warp * 16;
    int rowL = m0 + g, rowH = m0 + g + 8;

    unsigned qa[4][4];
#pragma unroll
    for (int kt = 0; kt < 4; kt++) {
        int k2 = kt * 16 + 2 * tig;
        qa[kt][0] = *(const unsigned*)(Qs + rowL * AKB + k2);
        qa[kt][1] = *(const unsigned*)(Qs + rowH * AKB + k2);
        qa[kt][2] = *(const unsigned*)(Qs + rowL * AKB + k2 + 8);
        qa[kt][3] = *(const unsigned*)(Qs + rowH * AKB + k2 + 8);
    }

    float mr0 = -1e30f, mr1 = -1e30f, sum0 = 0.f, sum1 = 0.f;
    float oacc[8][4] = {};

#pragma unroll
    for (int jc = 0; jc < 2; jc++) {
        int j0 = jc * 64;
        __syncthreads();   // K/V chunk reuse fence
        {
            int r2 = t >> 2;              // local j 0..63
            int q4o = (t & 3) * 16;       // d base
            const __nv_bfloat16* kr = qkv + ((long)(b * NN + j0 + r2)) * 1536 + 512
                                      + h * DH + q4o;
            const __nv_bfloat16* vr = kr + 512;
            __nv_bfloat16* kd = Ks + r2 * AKB + q4o;
            *(uint4*)(kd)     = *(const uint4*)(kr);
            *(uint4*)(kd + 8) = *(const uint4*)(kr + 8);
            __nv_bfloat16 vbuf[16];
            *(uint4*)(vbuf)     = *(const uint4*)(vr);
            *(uint4*)(vbuf + 8) = *(const uint4*)(vr + 8);
#pragma unroll
            for (int i = 0; i < 16; i++)
                Vt[(q4o + i) * AKB + r2] = vbuf[i];
        }
        __syncthreads();

        // S chunk = Q @ K_chunk^T
        float sacc[8][4] = {};
#pragma unroll
        for (int kt = 0; kt < 4; kt++) {
#pragma unroll
            for (int nt = 0; nt < 8; nt++) {
                unsigned bfr[2];
                const __nv_bfloat16* kp = Ks + (nt * 8 + g) * AKB + kt * 16 + 2 * tig;
                bfr[0] = *(const unsigned*)kp;
                bfr[1] = *(const unsigned*)(kp + 8);
                mma_bf16(sacc[nt], qa[kt], bfr);
            }
        }

        // scale + bias + chunk max
        const float* bL = bias + ((long)b * NN + rowL) * NN + j0 + 2 * tig;
        const float* bH = bias + ((long)b * NN + rowH) * NN + j0 + 2 * tig;
        float cm0 = -1e30f, cm1 = -1e30f;
#pragma unroll
        for (int nt = 0; nt < 8; nt++) {
            float2 b0 = *(const float2*)(bL + nt * 8);
            float2 b1 = *(const float2*)(bH + nt * 8);
            sacc[nt][0] = sacc[nt][0] * 0.125f + b0.x;
            sacc[nt][1] = sacc[nt][1] * 0.125f + b0.y;
            sacc[nt][2] = sacc[nt][2] * 0.125f + b1.x;
            sacc[nt][3] = sacc[nt][3] * 0.125f + b1.y;
            cm0 = fmaxf(cm0, fmaxf(sacc[nt][0], sacc[nt][1]));
            cm1 = fmaxf(cm1, fmaxf(sacc[nt][2], sacc[nt][3]));
        }
        cm0 = fmaxf(cm0, __shfl_xor_sync(0xffffffffu, cm0, 1));
        cm0 = fmaxf(cm0, __shfl_xor_sync(0xffffffffu, cm0, 2));
        cm1 = fmaxf(cm1, __shfl_xor_sync(0xffffffffu, cm1, 1));
        cm1 = fmaxf(cm1, __shfl_xor_sync(0xffffffffu, cm1, 2));

        float mn0 = fmaxf(mr0, cm0), mn1 = fmaxf(mr1, cm1);
        float c0 = __expf(mr0 - mn0), c1 = __expf(mr1 - mn1);
        mr0 = mn0; mr1 = mn1;
        sum0 *= c0; sum1 *= c1;
#pragma unroll
        for (int nt = 0; nt < 8; nt++) {
            oacc[nt][0] *= c0; oacc[nt][1] *= c0;
            oacc[nt][2] *= c1; oacc[nt][3] *= c1;
        }

        // exp + register-direct P packs + O += P @ V (per kt-pair)
#pragma unroll
        for (int kt = 0; kt < 4; kt++) {
            unsigned pa[4];
#pragma unroll
            for (int s = 0; s < 2; s++) {       // nt = 2*kt + s
                int nt = 2 * kt + s;
                float p0 = __expf(sacc[nt][0] - mr0);
                float p1 = __expf(sacc[nt][1] - mr0);
                float p2 = __expf(sacc[nt][2] - mr1);
                float p3 = __expf(sacc[nt][3] - mr1);
                sum0 += p0 + p1;
                sum1 += p2 + p3;
                __nv_bfloat162 tL = __floats2bfloat162_rn(p0, p1);
                __nv_bfloat162 tH = __floats2bfloat162_rn(p2, p3);
                pa[2 * s]     = *(unsigned*)&tL;
                pa[2 * s + 1] = *(unsigned*)&tH;
            }
            int k2 = kt * 16 + 2 * tig;
#pragma unroll
            for (int nt = 0; nt < 8; nt++) {
                unsigned bfr[2];
                const __nv_bfloat16* vp = Vt + (nt * 8 + g) * AKB + k2;
                bfr[0] = *(const unsigned*)vp;
                bfr[1] = *(const unsigned*)(vp + 8);
                mma_bf16(oacc[nt], pa, bfr);
            }
        }
    }

    sum0 += __shfl_xor_sync(0xffffffffu, sum0, 1);
    sum0 += __shfl_xor_sync(0xffffffffu, sum0, 2);
    sum1 += __shfl_xor_sync(0xffffffffu, sum1, 1);
    sum1 += __shfl_xor_sync(0xffffffffu, sum1, 2);

    float inv0 = 1.f / sum0, inv1 = 1.f / sum1;
    float* oL = o + ((long)(b * NN + rowL)) * INNER + h * DH;
    float* oH = o + ((long)(b * NN + rowH)) * INNER + h * DH;
#pragma unroll
    for (int nt = 0; nt < 8; nt++) {
        int c = nt * 8 + 2 * tig;
        float2 w0, w1;
        w0.x = oacc[nt][0] * inv0; w0.y = oacc[nt][1] * inv0;
        w1.x = oacc[nt][2] * inv1; w1.y = oacc[nt][3] * inv1;
        *(float2*)&oL[c] = w0;
        *(float2*)&oH[c] = w1;
    }
}

// ---------------------------------------------------------------------------
// Head: mean-pool over N, LayerNorm, dot with Wf
// ---------------------------------------------------------------------------
__global__ void head_kernel(const float* __restrict__ x, const float* __restrict__ g,
                            const float* __restrict__ be, const float* __restrict__ Wf,
                            const float* __restrict__ bf, float* __restrict__ out)
{
    __shared__ float pool[DLAT];
    int b = blockIdx.x;
    int t = threadIdx.x;     // 128 threads
    if (t < DLAT) {
        float s = 0.f;
        const float* xb = x + (long)b * NN * DLAT + t;
        for (int n = 0; n < NN; n++) s += xb[n * DLAT];
        pool[t] = s * (1.f / NN);
    }
    __syncthreads();
    if (t < 32) {
        float v0 = pool[t], v1 = pool[t + 32];
        float v2 = (t + 64 < DLAT) ? pool[t + 64] : 0.f;
        float s = v0 + v1 + v2;
#pragma unroll
        for (int o = 16; o; o >>= 1) s += __shfl_xor_sync(0xffffffffu, s, o);
        float mean = s * (1.f / DLAT);
        float d0 = v0 - mean, d1 = v1 - mean;
        float d2 = (t + 64 < DLAT) ? (v2 - mean) : 0.f;
        float vs = d0 * d0 + d1 * d1 + d2 * d2;
#pragma unroll
        for (int o = 16; o; o >>= 1) vs += __shfl_xor_sync(0xffffffffu, vs, o);
        float inv = rsqrtf(vs * (1.f / DLAT) + 1e-5f);
        float dot = (d0 * inv * g[t] + be[t]) * Wf[t]
                  + (d1 * inv * g[t + 32] + be[t + 32]) * Wf[t + 32];
        if (t + 64 < DLAT)
            dot += (d2 * inv * g[t + 64] + be[t + 64]) * Wf[t + 64];
#pragma unroll
        for (int o = 16; o; o >>= 1) dot += __shfl_xor_sync(0xffffffffu, dot, o);
        if (t == 0) out[b] = dot + bf[0];
    }
}

// ---------------------------------------------------------------------------
// Launch
// ---------------------------------------------------------------------------
extern "C" void kernel_launch(void* const* d_in, const int* in_sizes, int n_in,
                              void* d_out, int out_size)
{
    const int*   spatial_pos = (const int*)d_in[0];
    const int*   edge_input  = (const int*)d_in[1];
    const int*   x_nodes     = (const int*)d_in[2];
    const int*   indeg       = (const int*)d_in[3];
    const int*   outdeg      = (const int*)d_in[4];
    const float* atom_emb    = (const float*)d_in[5];
    const float* indeg_emb   = (const float*)d_in[6];
    const float* outdeg_emb  = (const float*)d_in[7];
    const float* edge_emb    = (const float*)d_in[8];
    const float* edge_dis_w  = (const float*)d_in[9];
    const float* spatial_emb = (const float*)d_in[10];
    const float* ln1_g = (const float*)d_in[11];
    const float* ln1_b = (const float*)d_in[12];
    const float* Wq    = (const float*)d_in[13];
    const float* Wkv   = (const float*)d_in[14];
    const float* Wo    = (const float*)d_in[15];
    const float* bo    = (const float*)d_in[16];
    const float* ln2_g = (const float*)d_in[17];
    const float* ln2_b = (const float*)d_in[18];
    const float* W1    = (const float*)d_in[19];
    const float* b1    = (const float*)d_in[20];
    const float* W2    = (const float*)d_in[21];
    const float* b2    = (const float*)d_in[22];
    const float* lnf_g = (const float*)d_in[23];
    const float* lnf_b = (const float*)d_in[24];
    const float* Wf    = (const float*)d_in[25];
    const float* bf    = (const float*)d_in[26];
    float* out = (float*)d_out;

    float *gx, *go, *gf, *gb;
    __nv_bfloat16* gqkv;
    cudaGetSymbolAddress((void**)&gx,   g_x);
    cudaGetSymbolAddress((void**)&gqkv, g_qkv);
    cudaGetSymbolAddress((void**)&go,   g_o);
    cudaGetSymbolAddress((void**)&gf,   g_f);
    cudaGetSymbolAddress((void**)&gb,   g_bias);

    cudaFuncSetAttribute(attn_kernel,
                         cudaFuncAttributeMaxDynamicSharedMemorySize, ATTN_SMEM);
    cudaFuncSetAttribute(panel_gemm<0>,
                         cudaFuncAttributeMaxDynamicSharedMemorySize, PANEL_SMEM);
    cudaFuncSetAttribute(panel_gemm<2>,
                         cudaFuncAttributeMaxDynamicSharedMemorySize, PANEL_SMEM);

    bias_kernel<<<BB * NN, 128>>>(spatial_pos, edge_input, edge_emb,
                                  edge_dis_w, spatial_emb, gb);
    embed_kernel<<<ROWS, DLAT>>>(x_nodes, indeg, outdeg,
                                 atom_emb, indeg_emb, outdeg_emb, gx);

    for (int l = 0; l < DEPTH; l++) {
        panel_gemm<0><<<dim3(24, ROWS / 128), 256, PANEL_SMEM>>>(
            gx, ln1_g + l * DLAT, ln1_b + l * DLAT,
            Wq + (long)l * DLAT * INNER, Wkv + (long)l * DLAT * 2 * INNER,
            INNER, 2 * INNER, nullptr, (void*)gqkv, 3 * INNER);
        attn_kernel<<<BB * NH, 256, ATTN_SMEM>>>(gqkv, gb, go);
        mma_gemm<1><<<dim3(2, ROWS / GBM), 256>>>(
            go, Wo + (long)l * INNER * DLAT, bo + l * DLAT, gx,
            gx, ROWS, INNER, DLAT, DLAT, 0);
        panel_gemm<2><<<dim3(3, ROWS / 128), 256, PANEL_SMEM>>>(
            gx, ln2_g + l * DLAT, ln2_b + l * DLAT,
            W1 + (long)l * DLAT * FFD, nullptr,
            FFD, 0, b1 + l * FFD, (void*)gf, FFD);
        mma_gemm<1><<<dim3(2, ROWS / GBM), 256>>>(
            gf, W2 + (long)l * FFD * DLAT, b2 + l * DLAT, gx,
            gx, ROWS, FFD, DLAT, DLAT, 0);
    }

    head_kernel<<<BB, 128>>>(gx, lnf_g, lnf_b, Wf, bf, out);
}

// round 17
// speedup vs baseline: 1.1138x; 1.0467x over previous
#include <cuda_runtime.h>
#include <cuda_bf16.h>
#include <math.h>

// Problem constants
#define BB 64
#define NN 128
#define DLAT 80
#define NH 8
#define DH 64
#define INNER 512
#define FFD 160
#define MHD 20
#define DEPTH 24
#define ROWS (BB * NN)   // 8192

// ---------------------------------------------------------------------------
// Scratch (device globals; no allocation allowed)
// ---------------------------------------------------------------------------
__device__ float g_x[ROWS * DLAT];                  // residual stream
__device__ __nv_bfloat16 g_qkv[ROWS * 3 * INNER];   // fused Q|K|V (bf16, stride 1536)
__device__ float g_o[ROWS * INNER];                 // attention output
__device__ float g_f[ROWS * FFD];                   // FF hidden
__device__ float g_bias[BB * NN * NN];              // graph attention bias

// ---------------------------------------------------------------------------
// helpers
// ---------------------------------------------------------------------------
__device__ __forceinline__ float to_tf32(float x)
{
    float r;
    asm("cvt.rna.tf32.f32 %0, %1;" : "=f"(r) : "f"(x));
    return r;
}

__device__ __forceinline__ void mma_tf32(float* c, const float* a, const float* b)
{
    asm volatile(
        "mma.sync.aligned.m16n8k8.row.col.f32.tf32.tf32.f32 "
        "{%0,%1,%2,%3}, {%4,%5,%6,%7}, {%8,%9}, {%0,%1,%2,%3};"
        : "+f"(c[0]), "+f"(c[1]), "+f"(c[2]), "+f"(c[3])
        : "r"(__float_as_uint(a[0])), "r"(__float_as_uint(a[1])),
          "r"(__float_as_uint(a[2])), "r"(__float_as_uint(a[3])),
          "r"(__float_as_uint(b[0])), "r"(__float_as_uint(b[1])));
}

__device__ __forceinline__ void mma_bf16(float* c, const unsigned* a, const unsigned* b)
{
    asm volatile(
        "mma.sync.aligned.m16n8k16.row.col.f32.bf16.bf16.f32 "
        "{%0,%1,%2,%3}, {%4,%5,%6,%7}, {%8,%9}, {%0,%1,%2,%3};"
        : "+f"(c[0]), "+f"(c[1]), "+f"(c[2]), "+f"(c[3])
        : "r"(a[0]), "r"(a[1]), "r"(a[2]), "r"(a[3]),
          "r"(b[0]), "r"(b[1]));
}

// ---------------------------------------------------------------------------
// Graph bias
// ---------------------------------------------------------------------------
__global__ void bias_kernel(const int* __restrict__ spatial_pos,
                            const int* __restrict__ edge_input,
                            const float* __restrict__ edge_emb,
                            const float* __restrict__ edge_dis_w,
                            const float* __restrict__ spatial_emb,
                            float* __restrict__ bias)
{
    __shared__ float s_edge[64];
    __shared__ float s_w[MHD];
    __shared__ float s_sp[40];
    int t = threadIdx.x;               // 128 threads
    if (t < 64) s_edge[t] = edge_emb[t];
    if (t < MHD) s_w[t] = edge_dis_w[t];
    if (t >= 64 && t < 104) s_sp[t - 64] = spatial_emb[t - 64];
    __syncthreads();

    long bi = blockIdx.x;              // b*N + i
    int j = t;
    const int* ei = edge_input + (bi * NN + j) * (MHD * 3);
    float acc = 0.f;
#pragma unroll
    for (int hh = 0; hh < MHD; hh++) {
        float e = (s_edge[ei[hh * 3 + 0]] + s_edge[ei[hh * 3 + 1]] +
                   s_edge[ei[hh * 3 + 2]]) * (1.f / 3.f);
        acc += e * s_w[hh];
    }
    int sp0 = spatial_pos[bi * NN + j];
    int sp = (sp0 == 0) ? 1 : sp0;
    sp = (sp > 1) ? sp - 1 : sp;
    sp = min(sp, MHD);
    bias[bi * NN + j] = acc / (float)sp + s_sp[sp0];
}

// ---------------------------------------------------------------------------
// Node embedding
// ---------------------------------------------------------------------------
__global__ void embed_kernel(const int* __restrict__ x_nodes,
                             const int* __restrict__ indeg,
                             const int* __restrict__ outdeg,
                             const float* __restrict__ atom_emb,
                             const float* __restrict__ indeg_emb,
                             const float* __restrict__ outdeg_emb,
                             float* __restrict__ x)
{
    int r = blockIdx.x;      // 8192 rows
    int d = threadIdx.x;     // 80
    int a = x_nodes[r], i = indeg[r], o = outdeg[r];
    x[(long)r * DLAT + d] = atom_emb[a * DLAT + d] + indeg_emb[i * DLAT + d]
                          + outdeg_emb[o * DLAT + d];
}

// ---------------------------------------------------------------------------
// Panel GEMM with fused LayerNorm (K = DLAT = 80 only). 3 blocks/SM.
//   EPI 0: store bf16 (QKV path)   EPI 2: gelu_exact(acc + bias[n]), fp32
// ---------------------------------------------------------------------------
#define PAST 84
#define PANEL_SMEM ((128 + 64) * PAST * 4)   // 64512 bytes

template <int EPI>
__global__ void __launch_bounds__(256, 3) panel_gemm(
    const float* __restrict__ X,
    const float* __restrict__ lng, const float* __restrict__ lnb,
    const float* __restrict__ Wa, const float* __restrict__ Wb,
    int NcA, int NcB,
    const float* __restrict__ bias,
    void* __restrict__ Cout, int ldc)
{
    extern __shared__ float sm[];
    float* As = sm;                // [128][84]
    float* Bs = sm + 128 * PAST;   // [64][84]

    int bm = blockIdx.y * 128;
    int n_glob = blockIdx.x * 64;
    const float* W; int Wn; int wcol;
    if (n_glob < NcA) { W = Wa; Wn = NcA; wcol = n_glob; }
    else             { W = Wb; Wn = NcB; wcol = n_glob - NcA; }
    int NcTot = NcA + NcB;

    int t = threadIdx.x;

    {   // A panel: load 128x80, fused LayerNorm, tf32 store
        int r = t >> 1, half = t & 1;
        const float* ar = X + (long)(bm + r) * DLAT + half * 40;
        float* ad = As + r * PAST + half * 40;
        float s = 0.f;
#pragma unroll
        for (int i = 0; i < 40; i += 4) {
            float4 a4 = *(const float4*)(ar + i);
            *(float4*)(ad + i) = a4;
            s += (a4.x + a4.y) + (a4.z + a4.w);
        }
        s += __shfl_xor_sync(0xffffffffu, s, 1);
        float mean = s * (1.f / DLAT);
        float vs = 0.f;
#pragma unroll
        for (int i = 0; i < 40; i++) { float d = ad[i] - mean; vs += d * d; }
        vs += __shfl_xor_sync(0xffffffffu, vs, 1);
        float inv = rsqrtf(vs * (1.f / DLAT) + 1e-5f);
        const float* gg = lng + half * 40;
        const float* bb = lnb + half * 40;
#pragma unroll
        for (int i = 0; i < 40; i++)
            ad[i] = to_tf32((ad[i] - mean) * inv * gg[i] + bb[i]);
    }

    {   // B panel: transpose-stage W[k][wcol+n] -> Bs[n][k] (tf32)
        int kr = t >> 4;          // 0..15
        int n0 = (t & 15) * 4;    // 0..60
#pragma unroll
        for (int kb = 0; kb < DLAT; kb += 16) {
            int k = kb + kr;
            float4 w4 = make_float4(0.f, 0.f, 0.f, 0.f);
            if (wcol + n0 < Wn) {
                const float* wp = W + (long)k * Wn + wcol + n0;
                if (wcol + n0 + 3 < Wn) {
                    w4 = *(const float4*)wp;
                } else {
                    w4.x = wp[0];
                    if (wcol + n0 + 1 < Wn) w4.y = wp[1];
                    if (wcol + n0 + 2 < Wn) w4.z = wp[2];
                }
            }
            Bs[(n0 + 0) * PAST + k] = to_tf32(w4.x);
            Bs[(n0 + 1) * PAST + k] = to_tf32(w4.y);
            Bs[(n0 + 2) * PAST + k] = to_tf32(w4.z);
            Bs[(n0 + 3) * PAST + k] = to_tf32(w4.w);
        }
    }
    __syncthreads();

    int warp = t >> 5, lane = t & 31;
    int g = lane >> 2, tig = lane & 3;
    int warpM = warp >> 1, warpN = warp & 1;

    float acc[2][4][4] = {};

#pragma unroll
    for (int kt = 0; kt < 10; kt++) {
        int kk = kt * 8;
        float af[2][4];
#pragma unroll
        for (int mt = 0; mt < 2; mt++) {
            int r = warpM * 32 + mt * 16;
            af[mt][0] = As[(r + g) * PAST + kk + tig];
            af[mt][1] = As[(r + g + 8) * PAST + kk + tig];
            af[mt][2] = As[(r + g) * PAST + kk + tig + 4];
            af[mt][3] = As[(r + g + 8) * PAST + kk + tig + 4];
        }
#pragma unroll
        for (int nt = 0; nt < 4; nt++) {
            float bf[2];
            int n = warpN * 32 + nt * 8 + g;
            bf[0] = Bs[n * PAST + kk + tig];
            bf[1] = Bs[n * PAST + kk + tig + 4];
#pragma unroll
            for (int mt = 0; mt < 2; mt++)
                mma_tf32(acc[mt][nt], af[mt], bf);
        }
    }

#pragma unroll
    for (int mt = 0; mt < 2; mt++) {
        long rL = bm + warpM * 32 + mt * 16 + g;
        long rH = rL + 8;
#pragma unroll
        for (int nt = 0; nt < 4; nt++) {
            int n = n_glob + warpN * 32 + nt * 8 + 2 * tig;
            if (n >= NcTot) continue;
            float v0 = acc[mt][nt][0], v1 = acc[mt][nt][1];
            float v2 = acc[mt][nt][2], v3 = acc[mt][nt][3];
            if (EPI == 0) {
                __nv_bfloat16* Cb = (__nv_bfloat16*)Cout;
                *(__nv_bfloat162*)&Cb[rL * ldc + n] = __floats2bfloat162_rn(v0, v1);
                *(__nv_bfloat162*)&Cb[rH * ldc + n] = __floats2bfloat162_rn(v2, v3);
            } else {
                float b0 = bias[n], b1 = bias[n + 1];
                v0 += b0; v1 += b1; v2 += b0; v3 += b1;
                v0 = 0.5f * v0 * (1.f + erff(v0 * 0.70710678118654752f));
                v1 = 0.5f * v1 * (1.f + erff(v1 * 0.70710678118654752f));
                v2 = 0.5f * v2 * (1.f + erff(v2 * 0.70710678118654752f));
                v3 = 0.5f * v3 * (1.f + erff(v3 * 0.70710678118654752f));
                float* Cf = (float*)Cout;
                float2 w0, w1;
                w0.x = v0; w0.y = v1;
                w1.x = v2; w1.y = v3;
                *(float2*)&Cf[rL * ldc + n] = w0;
                *(float2*)&Cf[rH * ldc + n] = w1;
            }
        }
    }
}

// ---------------------------------------------------------------------------
// Chunked tf32 GEMM for Wo (K=512) and FF2 (K=160). BM=64, BK=32.
// Same ascending k8-tile order as BK=16 -> bitwise identical accumulation.
// Requires K % 32 == 0 (512, 160 OK).
//   EPI 1: +bias[n]+res[m,n]
// ---------------------------------------------------------------------------
#define GBM 64
#define GBN 64
#define GBK 32
#define GAS 36
#define GBS 36

template <int EPI>
__global__ void __launch_bounds__(256) mma_gemm(
    const float* __restrict__ A, const float* __restrict__ W,
    const float* __restrict__ bias, const float* __restrict__ res,
    float* __restrict__ C, int M, int K, int Nc, int ldc, int coff)
{
    __shared__ float As[GBM * GAS];
    __shared__ float Bs[GBN * GBS];
    int bm = blockIdx.y * GBM;
    int bn = blockIdx.x * GBN;
    int tid = threadIdx.x;
    int warp = tid >> 5, lane = tid & 31;
    int g = lane >> 2, tig = lane & 3;
    int warpM = warp >> 2, warpN = warp & 3;

    float acc[2][2][4] = {};

    for (int k0 = 0; k0 < K; k0 += GBK) {
        {   // A tile: 64 rows x 32 k; thread loads 8 consecutive k (2 float4)
            int m = tid >> 2;
            int kq = (tid & 3) * 8;
            const float* ap = A + (long)(bm + m) * K + k0 + kq;
            float4 a0 = *(const float4*)ap;
            float4 a1 = *(const float4*)(ap + 4);
            float* ad = As + m * GAS + kq;
            ad[0] = to_tf32(a0.x); ad[1] = to_tf32(a0.y);
            ad[2] = to_tf32(a0.z); ad[3] = to_tf32(a0.w);
            ad[4] = to_tf32(a1.x); ad[5] = to_tf32(a1.y);
            ad[6] = to_tf32(a1.z); ad[7] = to_tf32(a1.w);
        }
        {   // B tile: 32 k x 64 n, transposed -> Bs[n][k]; 2 k-rows per thread
            int n0 = (tid & 15) * 4;
#pragma unroll
            for (int kb = 0; kb < 2; kb++) {
                int kr = (tid >> 4) + kb * 16;
                const float* wp = W + (long)(k0 + kr) * Nc + bn + n0;
                float4 w4 = make_float4(0.f, 0.f, 0.f, 0.f);
                if (bn + n0 + 3 < Nc) {
                    w4 = *(const float4*)wp;
                } else if (bn + n0 < Nc) {
                    w4.x = wp[0];
                    if (bn + n0 + 1 < Nc) w4.y = wp[1];
                    if (bn + n0 + 2 < Nc) w4.z = wp[2];
                }
                Bs[(n0 + 0) * GBS + kr] = to_tf32(w4.x);
                Bs[(n0 + 1) * GBS + kr] = to_tf32(w4.y);
                Bs[(n0 + 2) * GBS + kr] = to_tf32(w4.z);
                Bs[(n0 + 3) * GBS + kr] = to_tf32(w4.w);
            }
        }
        __syncthreads();
#pragma unroll
        for (int kt = 0; kt < 4; kt++) {
            int kk = kt * 8;
            float af[2][4];
#pragma unroll
            for (int mt = 0; mt < 2; mt++) {
                int r = warpM * 32 + mt * 16;
                af[mt][0] = As[(r + g) * GAS + kk + tig];
                af[mt][1] = As[(r + g + 8) * GAS + kk + tig];
                af[mt][2] = As[(r + g) * GAS + kk + tig + 4];
                af[mt][3] = As[(r + g + 8) * GAS + kk + tig + 4];
            }
#pragma unroll
            for (int nt = 0; nt < 2; nt++) {
                float bf[2];
                int n = warpN * 16 + nt * 8 + g;
                bf[0] = Bs[n * GBS + kk + tig];
                bf[1] = Bs[n * GBS + kk + tig + 4];
#pragma unroll
                for (int mt = 0; mt < 2; mt++)
                    mma_tf32(acc[mt][nt], af[mt], bf);
            }
        }
        __syncthreads();
    }

#pragma unroll
    for (int mt = 0; mt < 2; mt++) {
        long rL = bm + warpM * 32 + mt * 16 + g;
        long rH = rL + 8;
#pragma unroll
        for (int nt = 0; nt < 2; nt++) {
            int n = bn + warpN * 16 + nt * 8 + 2 * tig;
            if (n >= Nc) continue;
            float v0 = acc[mt][nt][0], v1 = acc[mt][nt][1];
            float v2 = acc[mt][nt][2], v3 = acc[mt][nt][3];
            if (EPI == 1) {
                float b0 = bias[n], b1 = bias[n + 1];
                const float* rL_p = res + rL * Nc + n;
                const float* rH_p = res + rH * Nc + n;
                v0 += b0 + rL_p[0]; v1 += b1 + rL_p[1];
                v2 += b0 + rH_p[0]; v3 += b1 + rH_p[1];
            }
            float2 w0, w1;
            w0.x = v0; w0.y = v1;
            w1.x = v2; w1.y = v3;
            *(float2*)&C[rL * ldc + coff + n] = w0;
            *(float2*)&C[rH * ldc + coff + n] = w1;
        }
    }
}

// ---------------------------------------------------------------------------
// bf16 flash attention, register-direct P; qkv bf16 in global.
// Smem: Ks[64][72] + Vt[64][72] + Qs[128][72] (bf16) = 36864 B -> 2 blocks/SM.
// ---------------------------------------------------------------------------
#define AKB 72
#define ATTN_SMEM ((64 + 64 + 128) * AKB * 2)   // 36864 bytes

__global__ void __launch_bounds__(256, 2) attn_kernel(
    const __nv_bfloat16* __restrict__ qkv, const float* __restrict__ bias,
    float* __restrict__ o)
{
    extern __shared__ float sm[];
    __nv_bfloat16* Ks = (__nv_bfloat16*)sm;        // [64][72]  K chunk (rows j)
    __nv_bfloat16* Vt = Ks + 64 * AKB;             // [64][72]  V chunk (rows d, cols j)
    __nv_bfloat16* Qs = Vt + 64 * AKB;             // [128][72] Q staging

    int bh = blockIdx.x;
    int b = bh >> 3, h = bh & 7;
    int t = threadIdx.x;

    // Stage Q (already bf16)
    {
        int r = t >> 1, half = t & 1;
        const __nv_bfloat16* qr = qkv + ((long)(b * NN + r)) * 1536 + h * DH + half * 32;
        __nv_bfloat16* qd = Qs + r * AKB + half * 32;
#pragma unroll
        for (int i = 0; i < 32; i += 8)
            *(uint4*)(qd + i) = *(const uint4*)(qr + i);
    }
    __syncthreads();

    int warp = t >> 5, lane = t & 31;
    int g = lane >> 2, tig = lane & 3;
    int m0 = warp * 16;
    int rowL = m0 + g, rowH = m0 + g + 8;

    unsigned qa[4][4];
#pragma unroll
    for (int kt = 0; kt < 4; kt++) {
        int k2 = kt * 16 + 2 * tig;
        qa[kt][0] = *(const unsigned*)(Qs + rowL * AKB + k2);
        qa[kt][1] = *(const unsigned*)(Qs + rowH * AKB + k2);
        qa[kt][2] = *(const unsigned*)(Qs + rowL * AKB + k2 + 8);
        qa[kt][3] = *(const unsigned*)(Qs + rowH * AKB + k2 + 8);
    }

    float mr0 = -1e30f, mr1 = -1e30f, sum0 = 0.f, sum1 = 0.f;
    float oacc[8][4] = {};

#pragma unroll
    for (int jc = 0; jc < 2; jc++) {
        int j0 = jc * 64;
        __syncthreads();   // K/V chunk reuse fence
        {
            int r2 = t >> 2;              // local j 0..63
            int q4o = (t & 3) * 16;       // d base
            const __nv_bfloat16* kr = qkv + ((long)(b * NN + j0 + r2)) * 1536 + 512
                                      + h * DH + q4o;
            const __nv_bfloat16* vr = kr + 512;
            __nv_bfloat16* kd = Ks + r2 * AKB + q4o;
            *(uint4*)(kd)     = *(const uint4*)(kr);
            *(uint4*)(kd + 8) = *(const uint4*)(kr + 8);
            __nv_bfloat16 vbuf[16];
            *(uint4*)(vbuf)     = *(const uint4*)(vr);
            *(uint4*)(vbuf + 8) = *(const uint4*)(vr + 8);
#pragma unroll
            for (int i = 0; i < 16; i++)
                Vt[(q4o + i) * AKB + r2] = vbuf[i];
        }
        __syncthreads();

        // S chunk = Q @ K_chunk^T
        float sacc[8][4] = {};
#pragma unroll
        for (int kt = 0; kt < 4; kt++) {
#pragma unroll
            for (int nt = 0; nt < 8; nt++) {
                unsigned bfr[2];
                const __nv_bfloat16* kp = Ks + (nt * 8 + g) * AKB + kt * 16 + 2 * tig;
                bfr[0] = *(const unsigned*)kp;
                bfr[1] = *(const unsigned*)(kp + 8);
                mma_bf16(sacc[nt], qa[kt], bfr);
            }
        }

        // scale + bias + chunk max
        const float* bL = bias + ((long)b * NN + rowL) * NN + j0 + 2 * tig;
        const float* bH = bias + ((long)b * NN + rowH) * NN + j0 + 2 * tig;
        float cm0 = -1e30f, cm1 = -1e30f;
#pragma unroll
        for (int nt = 0; nt < 8; nt++) {
            float2 b0 = *(const float2*)(bL + nt * 8);
            float2 b1 = *(const float2*)(bH + nt * 8);
            sacc[nt][0] = sacc[nt][0] * 0.125f + b0.x;
            sacc[nt][1] = sacc[nt][1] * 0.125f + b0.y;
            sacc[nt][2] = sacc[nt][2] * 0.125f + b1.x;
            sacc[nt][3] = sacc[nt][3] * 0.125f + b1.y;
            cm0 = fmaxf(cm0, fmaxf(sacc[nt][0], sacc[nt][1]));
            cm1 = fmaxf(cm1, fmaxf(sacc[nt][2], sacc[nt][3]));
        }
        cm0 = fmaxf(cm0, __shfl_xor_sync(0xffffffffu, cm0, 1));
        cm0 = fmaxf(cm0, __shfl_xor_sync(0xffffffffu, cm0, 2));
        cm1 = fmaxf(cm1, __shfl_xor_sync(0xffffffffu, cm1, 1));
        cm1 = fmaxf(cm1, __shfl_xor_sync(0xffffffffu, cm1, 2));

        float mn0 = fmaxf(mr0, cm0), mn1 = fmaxf(mr1, cm1);
        float c0 = __expf(mr0 - mn0), c1 = __expf(mr1 - mn1);
        mr0 = mn0; mr1 = mn1;
        sum0 *= c0; sum1 *= c1;
#pragma unroll
        for (int nt = 0; nt < 8; nt++) {
            oacc[nt][0] *= c0; oacc[nt][1] *= c0;
            oacc[nt][2] *= c1; oacc[nt][3] *= c1;
        }

        // exp + register-direct P packs + O += P @ V (per kt-pair)
#pragma unroll
        for (int kt = 0; kt < 4; kt++) {
            unsigned pa[4];
#pragma unroll
            for (int s = 0; s < 2; s++) {       // nt = 2*kt + s
                int nt = 2 * kt + s;
                float p0 = __expf(sacc[nt][0] - mr0);
                float p1 = __expf(sacc[nt][1] - mr0);
                float p2 = __expf(sacc[nt][2] - mr1);
                float p3 = __expf(sacc[nt][3] - mr1);
                sum0 += p0 + p1;
                sum1 += p2 + p3;
                __nv_bfloat162 tL = __floats2bfloat162_rn(p0, p1);
                __nv_bfloat162 tH = __floats2bfloat162_rn(p2, p3);
                pa[2 * s]     = *(unsigned*)&tL;
                pa[2 * s + 1] = *(unsigned*)&tH;
            }
            int k2 = kt * 16 + 2 * tig;
#pragma unroll
            for (int nt = 0; nt < 8; nt++) {
                unsigned bfr[2];
                const __nv_bfloat16* vp = Vt + (nt * 8 + g) * AKB + k2;
                bfr[0] = *(const unsigned*)vp;
                bfr[1] = *(const unsigned*)(vp + 8);
                mma_bf16(oacc[nt], pa, bfr);
            }
        }
    }

    sum0 += __shfl_xor_sync(0xffffffffu, sum0, 1);
    sum0 += __shfl_xor_sync(0xffffffffu, sum0, 2);
    sum1 += __shfl_xor_sync(0xffffffffu, sum1, 1);
    sum1 += __shfl_xor_sync(0xffffffffu, sum1, 2);

    float inv0 = 1.f / sum0, inv1 = 1.f / sum1;
    float* oL = o + ((long)(b * NN + rowL)) * INNER + h * DH;
    float* oH = o + ((long)(b * NN + rowH)) * INNER + h * DH;
#pragma unroll
    for (int nt = 0; nt < 8; nt++) {
        int c = nt * 8 + 2 * tig;
        float2 w0, w1;
        w0.x = oacc[nt][0] * inv0; w0.y = oacc[nt][1] * inv0;
        w1.x = oacc[nt][2] * inv1; w1.y = oacc[nt][3] * inv1;
        *(float2*)&oL[c] = w0;
        *(float2*)&oH[c] = w1;
    }
}

// ---------------------------------------------------------------------------
// Head: mean-pool over N, LayerNorm, dot with Wf
// ---------------------------------------------------------------------------
__global__ void head_kernel(const float* __restrict__ x, const float* __restrict__ g,
                            const float* __restrict__ be, const float* __restrict__ Wf,
                            const float* __restrict__ bf, float* __restrict__ out)
{
    __shared__ float pool[DLAT];
    int b = blockIdx.x;
    int t = threadIdx.x;     // 128 threads
    if (t < DLAT) {
        float s = 0.f;
        const float* xb = x + (long)b * NN * DLAT + t;
        for (int n = 0; n < NN; n++) s += xb[n * DLAT];
        pool[t] = s * (1.f / NN);
    }
    __syncthreads();
    if (t < 32) {
        float v0 = pool[t], v1 = pool[t + 32];
        float v2 = (t + 64 < DLAT) ? pool[t + 64] : 0.f;
        float s = v0 + v1 + v2;
#pragma unroll
        for (int o = 16; o; o >>= 1) s += __shfl_xor_sync(0xffffffffu, s, o);
        float mean = s * (1.f / DLAT);
        float d0 = v0 - mean, d1 = v1 - mean;
        float d2 = (t + 64 < DLAT) ? (v2 - mean) : 0.f;
        float vs = d0 * d0 + d1 * d1 + d2 * d2;
#pragma unroll
        for (int o = 16; o; o >>= 1) vs += __shfl_xor_sync(0xffffffffu, vs, o);
        float inv = rsqrtf(vs * (1.f / DLAT) + 1e-5f);
        float dot = (d0 * inv * g[t] + be[t]) * Wf[t]
                  + (d1 * inv * g[t + 32] + be[t + 32]) * Wf[t + 32];
        if (t + 64 < DLAT)
            dot += (d2 * inv * g[t + 64] + be[t + 64]) * Wf[t + 64];
#pragma unroll
        for (int o = 16; o; o >>= 1) dot += __shfl_xor_sync(0xffffffffu, dot, o);
        if (t == 0) out[b] = dot + bf[0];
    }
}

// ---------------------------------------------------------------------------
// Launch
// ---------------------------------------------------------------------------
extern "C" void kernel_launch(void* const* d_in, const int* in_sizes, int n_in,
                              void* d_out, int out_size)
{
    const int*   spatial_pos = (const int*)d_in[0];
    const int*   edge_input  = (const int*)d_in[1];
    const int*   x_nodes     = (const int*)d_in[2];
    const int*   indeg       = (const int*)d_in[3];
    const int*   outdeg      = (const int*)d_in[4];
    const float* atom_emb    = (const float*)d_in[5];
    const float* indeg_emb   = (const float*)d_in[6];
    const float* outdeg_emb  = (const float*)d_in[7];
    const float* edge_emb    = (const float*)d_in[8];
    const float* edge_dis_w  = (const float*)d_in[9];
    const float* spatial_emb = (const float*)d_in[10];
    const float* ln1_g = (const float*)d_in[11];
    const float* ln1_b = (const float*)d_in[12];
    const float* Wq    = (const float*)d_in[13];
    const float* Wkv   = (const float*)d_in[14];
    const float* Wo    = (const float*)d_in[15];
    const float* bo    = (const float*)d_in[16];
    const float* ln2_g = (const float*)d_in[17];
    const float* ln2_b = (const float*)d_in[18];
    const float* W1    = (const float*)d_in[19];
    const float* b1    = (const float*)d_in[20];
    const float* W2    = (const float*)d_in[21];
    const float* b2    = (const float*)d_in[22];
    const float* lnf_g = (const float*)d_in[23];
    const float* lnf_b = (const float*)d_in[24];
    const float* Wf    = (const float*)d_in[25];
    const float* bf    = (const float*)d_in[26];
    float* out = (float*)d_out;

    float *gx, *go, *gf, *gb;
    __nv_bfloat16* gqkv;
    cudaGetSymbolAddress((void**)&gx,   g_x);
    cudaGetSymbolAddress((void**)&gqkv, g_qkv);
    cudaGetSymbolAddress((void**)&go,   g_o);
    cudaGetSymbolAddress((void**)&gf,   g_f);
    cudaGetSymbolAddress((void**)&gb,   g_bias);

    cudaFuncSetAttribute(attn_kernel,
                         cudaFuncAttributeMaxDynamicSharedMemorySize, ATTN_SMEM);
    cudaFuncSetAttribute(panel_gemm<0>,
                         cudaFuncAttributeMaxDynamicSharedMemorySize, PANEL_SMEM);
    cudaFuncSetAttribute(panel_gemm<2>,
                         cudaFuncAttributeMaxDynamicSharedMemorySize, PANEL_SMEM);

    bias_kernel<<<BB * NN, 128>>>(spatial_pos, edge_input, edge_emb,
                                  edge_dis_w, spatial_emb, gb);
    embed_kernel<<<ROWS, DLAT>>>(x_nodes, indeg, outdeg,
                                 atom_emb, indeg_emb, outdeg_emb, gx);

    for (int l = 0; l < DEPTH; l++) {
        panel_gemm<0><<<dim3(24, ROWS / 128), 256, PANEL_SMEM>>>(
            gx, ln1_g + l * DLAT, ln1_b + l * DLAT,
            Wq + (long)l * DLAT * INNER, Wkv + (long)l * DLAT * 2 * INNER,
            INNER, 2 * INNER, nullptr, (void*)gqkv, 3 * INNER);
        attn_kernel<<<BB * NH, 256, ATTN_SMEM>>>(gqkv, gb, go);
        mma_gemm<1><<<dim3(2, ROWS / GBM), 256>>>(
            go, Wo + (long)l * INNER * DLAT, bo + l * DLAT, gx,
            gx, ROWS, INNER, DLAT, DLAT, 0);
        panel_gemm<2><<<dim3(3, ROWS / 128), 256, PANEL_SMEM>>>(
            gx, ln2_g + l * DLAT, ln2_b + l * DLAT,
            W1 + (long)l * DLAT * FFD, nullptr,
            FFD, 0, b1 + l * FFD, (void*)gf, FFD);
        mma_gemm<1><<<dim3(2, ROWS / GBM), 256>>>(
            gf, W2 + (long)l * FFD * DLAT, b2 + l * DLAT, gx,
            gx, ROWS, FFD, DLAT, DLAT, 0);
    }

    head_kernel<<<BB, 128>>>(gx, lnf_g, lnf_b, Wf, bf, out);
}